// round 13
// baseline (speedup 1.0000x reference)
#include <cuda_runtime.h>
#include <cuda_fp16.h>
#include <math.h>
#include <stdint.h>

// ---------------- problem constants ----------------
#define BATCH 1024
#define NT    8192
#define NS    8192
#define DIM   1024
#define NC    10
#define TEMP  100.0f
#define SPLITK 9

// ---------------- scratch (device globals; no allocation) ----------------
__device__ float g_logits[(size_t)BATCH * NT];   // 32 MB
__device__ float g_xsp[(size_t)SPLITK * BATCH * DIM];  // split-K partials, 36 MB
__device__ float g_tn[NT];
__device__ float g_sn[NS];
__device__ float g_xn[BATCH];
__device__ float g_xsn[BATCH];
__device__ float g_t[BATCH * NC];
__device__ float g_atlT[NC * NS];                // atl transposed [NC, NS]
// fp16 split-2 operand buffers (hi at offset 0, lo at offset SZ)
__device__ __half g_x2  [(size_t)2 * BATCH * DIM];
__device__ __half g_tf2 [(size_t)2 * NT * DIM];
__device__ __half g_sf2 [(size_t)2 * NS * DIM];
__device__ __half g_asfT2[(size_t)2 * DIM * NT];   // asf transposed: [DIM, NT]
__device__ __half g_w2  [(size_t)2 * BATCH * NT];
__device__ __half g_xs2 [(size_t)2 * BATCH * DIM];

// ===================== asm helpers (sm_80-era PTX; compiles for compute_103) =====================
__device__ __forceinline__ uint32_t smem_to_u32(const void* smem_ptr) {
    uint32_t addr;
    asm("{ .reg .u64 tmp; cvta.to.shared.u64 tmp, %1; cvt.u32.u64 %0, tmp; }"
        : "=r"(addr) : "l"(smem_ptr));
    return addr;
}
#define CP_ASYNC_CG16(dst, src) \
    asm volatile("cp.async.cg.shared.global [%0], [%1], 16;" :: "r"(dst), "l"(src))
#define CP_COMMIT() asm volatile("cp.async.commit_group;" ::: "memory")
#define CP_WAIT(n)  asm volatile("cp.async.wait_group %0;" :: "n"(n) : "memory")
#define LDSM_X4(r0, r1, r2, r3, addr) \
    asm volatile("ldmatrix.sync.aligned.m8n8.x4.shared.b16 {%0,%1,%2,%3}, [%4];" \
        : "=r"(r0), "=r"(r1), "=r"(r2), "=r"(r3) : "r"(addr))
#define MMA_16816(d, a, b) \
    asm volatile("mma.sync.aligned.m16n8k16.row.col.f32.f16.f16.f32 " \
        "{%0,%1,%2,%3}, {%4,%5,%6,%7}, {%8,%9}, {%0,%1,%2,%3};" \
        : "+f"((d)[0]), "+f"((d)[1]), "+f"((d)[2]), "+f"((d)[3]) \
        : "r"((a)[0]), "r"((a)[1]), "r"((a)[2]), "r"((a)[3]), \
          "r"((b)[0]), "r"((b)[1]))

// ===================== fp16 split-2 =====================
__device__ __forceinline__ void split2_one(float x, __half& h0, __half& h1) {
    h0 = __float2half_rn(x);
    h1 = __float2half_rn(x - __half2float(h0));
}

// fused: row squared-norm + split-2 (one pass over X). X: [R, 1024]; 256 thr/row.
__global__ void norm_split2_kernel(const float* __restrict__ X,
                                   __half* __restrict__ O0,
                                   __half* __restrict__ O1,
                                   float* __restrict__ norms) {
    int row = blockIdx.x;
    int tid = threadIdx.x;
    const float* xr = X + (size_t)row * DIM;
    float4 v = *reinterpret_cast<const float4*>(xr + tid * 4);
    float s = v.x * v.x + v.y * v.y + v.z * v.z + v.w * v.w;
    __half a0, a1, b0, b1, c0, c1, d0, d1;
    split2_one(v.x, a0, a1);
    split2_one(v.y, b0, b1);
    split2_one(v.z, c0, c1);
    split2_one(v.w, d0, d1);
    size_t o = (size_t)row * DIM + tid * 4;
    *reinterpret_cast<__half2*>(O0 + o)     = __halves2half2(a0, b0);
    *reinterpret_cast<__half2*>(O0 + o + 2) = __halves2half2(c0, d0);
    *reinterpret_cast<__half2*>(O1 + o)     = __halves2half2(a1, b1);
    *reinterpret_cast<__half2*>(O1 + o + 2) = __halves2half2(c1, d1);
    #pragma unroll
    for (int off = 16; off > 0; off >>= 1) s += __shfl_xor_sync(0xffffffffu, s, off);
    __shared__ float ws[8];
    if ((tid & 31) == 0) ws[tid >> 5] = s;
    __syncthreads();
    if (tid == 0) {
        float t = 0.f;
        #pragma unroll
        for (int i = 0; i < 8; i++) t += ws[i];
        norms[row] = t;
    }
}

// transpose + split2: X [R, Cc] fp32 -> O* [Cc, R] fp16.  32x32 tiles, 256 threads.
__global__ void split2T_kernel(const float* __restrict__ X,
                               __half* __restrict__ O0,
                               __half* __restrict__ O1, int R, int Cc) {
    __shared__ float t[32][33];
    int tx = threadIdx.x & 31;
    int ty = threadIdx.x >> 5;
    int r0 = blockIdx.y * 32;
    int c0 = blockIdx.x * 32;
    #pragma unroll
    for (int yy = 0; yy < 4; yy++) {
        int r = ty * 4 + yy;
        t[r][tx] = X[(size_t)(r0 + r) * Cc + c0 + tx];
    }
    __syncthreads();
    int p = tx & 15;
    int half = tx >> 4;
    #pragma unroll
    for (int yy = 0; yy < 2; yy++) {
        int j = ty * 2 + half + yy * 16;
        float v0 = t[p * 2][j], v1 = t[p * 2 + 1][j];
        __half h0, l0, h1, l1;
        split2_one(v0, h0, l0);
        split2_one(v1, h1, l1);
        size_t o = (size_t)(c0 + j) * R + r0 + p * 2;
        *reinterpret_cast<__half2*>(O0 + o) = __halves2half2(h0, h1);
        *reinterpret_cast<__half2*>(O1 + o) = __halves2half2(l0, l1);
    }
}

// tiny: atl [NS, NC] -> atlT [NC, NS]
__global__ void atlT_kernel(const float* __restrict__ atl, float* __restrict__ atlT) {
    int j = blockIdx.x * blockDim.x + threadIdx.x;
    if (j >= NS) return;
    #pragma unroll
    for (int c = 0; c < NC; c++) atlT[(size_t)c * NS + j] = atl[(size_t)j * NC + c];
}

// ===================== mma.sync fp16 split-2 GEMM (uneven split-K capable) =====================
// acc = A0*B0 + A0*B1 + A1*B0   (A = A0 + A1, B = B0 + B1; drop A1*B1)
// MODE 0: C = acc;  MODE 1: C = -T*sqrt(...);  MODE 2: MODE1 + label cost
// blockIdx.z selects a K-chunk range (computed in-kernel from gridDim.z);
// output goes to C + z*czstride.
#define KSTRIDE 40   // 32 used + 8 pad (fp16 elems) -> conflict-free ldmatrix

template<int BM, int BN, int THREADS, int STAGES>
__device__ __forceinline__ void load_stage_fn(
    const __half* __restrict__ A0g, const __half* __restrict__ A1g,
    const __half* __restrict__ B0g, const __half* __restrict__ B1g,
    uint32_t smem_u32, int st, int k0, int row0, int col0, int K, int tid)
{
    constexpr int A_STAGE = 2 * BM * KSTRIDE;
    constexpr int B_STAGE = 2 * BN * KSTRIDE;
    constexpr int B_BASE  = STAGES * A_STAGE;
    constexpr int TOT_A = BM * 8;
    constexpr int CPT = (BM + BN) * 8 / THREADS;
    #pragma unroll
    for (int t = 0; t < CPT; t++) {
        int i = tid + t * THREADS;
        if (i < TOT_A) {
            int sp = i / (BM * 4);
            int rr = (i >> 2) % BM;
            int kc = i & 3;
            const __half* g = sp ? A1g : A0g;
            const __half* src = g + (size_t)(row0 + rr) * K + k0 + kc * 8;
            uint32_t dst = smem_u32 + 2u * (uint32_t)(
                st * A_STAGE + (sp * BM + rr) * KSTRIDE + kc * 8);
            CP_ASYNC_CG16(dst, src);
        } else {
            int j = i - TOT_A;
            int sp = j / (BN * 4);
            int rr = (j >> 2) % BN;
            int kc = j & 3;
            const __half* g = sp ? B1g : B0g;
            const __half* src = g + (size_t)(col0 + rr) * K + k0 + kc * 8;
            uint32_t dst = smem_u32 + 2u * (uint32_t)(
                B_BASE + st * B_STAGE + (sp * BN + rr) * KSTRIDE + kc * 8);
            CP_ASYNC_CG16(dst, src);
        }
    }
}

template<int BM, int BN, int WM, int WN, int STAGES, int MODE>
__global__ void __launch_bounds__((BM / WM) * (BN / WN) * 32, ((BM / WM) * (BN / WN) == 4) ? 2 : 1)
mma_gemm_kernel(const __half* __restrict__ A0g, const __half* __restrict__ A1g,
                const __half* __restrict__ B0g, const __half* __restrict__ B1g,
                float* __restrict__ C, int N, int K, size_t czstride,
                const float* __restrict__ rnA, const float* __restrict__ rnB,
                const float* __restrict__ Tm, const float* __restrict__ SHL)
{
    constexpr int THREADS = (BM / WM) * (BN / WN) * 32;
    constexpr int MB = WM / 16;
    constexpr int NB = WN / 8;
    constexpr int NB2 = WN / 16;
    constexpr int A_STAGE = 2 * BM * KSTRIDE;
    constexpr int B_STAGE = 2 * BN * KSTRIDE;
    constexpr int B_BASE  = STAGES * A_STAGE;
    constexpr int TILE_ELEMS = STAGES * (A_STAGE + B_STAGE);

    extern __shared__ char smem[];
    const uint32_t smem_u32 = smem_to_u32(smem);
    const int tid = threadIdx.x;
    const int wid = tid >> 5;
    const int lane = tid & 31;
    const int warps_n = BN / WN;
    const int wm0 = (wid / warps_n) * WM;
    const int wn0 = (wid % warps_n) * WN;
    const int row0 = blockIdx.y * BM;
    const int col0 = blockIdx.x * BN;

    // uneven split-K: distribute (K/32) chunks over gridDim.z
    const int tc = K >> 5;
    const int zb = tc / gridDim.z;
    const int zr = tc % gridDim.z;
    const int z  = blockIdx.z;
    const int nch   = zb + (z < (int)zr ? 1 : 0);
    const int kbase = 32 * (z * zb + (z < (int)zr ? z : (int)zr));
    float* Cz = C + (size_t)z * czstride;

    float* sTm  = reinterpret_cast<float*>(smem + 2 * TILE_ELEMS);
    float* sShl = sTm + BM * NC;
    if (MODE == 2) {
        for (int i = tid; i < BM * NC; i += THREADS)
            sTm[i] = __ldg(&Tm[(size_t)(row0 + i / NC) * NC + (i % NC)]);
        for (int i = tid; i < BN * NC; i += THREADS)
            sShl[i] = __ldg(&SHL[(size_t)(col0 + i / NC) * NC + (i % NC)]);
    }

    float acc[MB][NB][4];
    #pragma unroll
    for (int i = 0; i < MB; i++)
        #pragma unroll
        for (int j = 0; j < NB; j++)
            #pragma unroll
            for (int q = 0; q < 4; q++) acc[i][j][q] = 0.f;

    #pragma unroll
    for (int s = 0; s < STAGES - 1; s++) {
        if (s < nch) {
            load_stage_fn<BM, BN, THREADS, STAGES>(A0g, A1g, B0g, B1g, smem_u32,
                                                   s, kbase + (s << 5), row0, col0, K, tid);
        }
        CP_COMMIT();
    }

    const int lrow = lane & 15;
    const int lcol = (lane >> 4) << 3;

    for (int c = 0; c < nch; c++) {
        CP_WAIT(STAGES - 2);
        __syncthreads();
        int pf = c + STAGES - 1;
        if (pf < nch)
            load_stage_fn<BM, BN, THREADS, STAGES>(A0g, A1g, B0g, B1g, smem_u32,
                                                   pf % STAGES, kbase + (pf << 5),
                                                   row0, col0, K, tid);
        CP_COMMIT();
        const int st = c % STAGES;

        #pragma unroll
        for (int s16 = 0; s16 < 32; s16 += 16) {
            uint32_t Af[2][MB][4];
            #pragma unroll
            for (int sp = 0; sp < 2; sp++)
                #pragma unroll
                for (int mb = 0; mb < MB; mb++) {
                    uint32_t addr = smem_u32 + 2u * (uint32_t)(
                        st * A_STAGE + (sp * BM + wm0 + mb * 16 + lrow) * KSTRIDE + s16 + lcol);
                    LDSM_X4(Af[sp][mb][0], Af[sp][mb][1], Af[sp][mb][2], Af[sp][mb][3], addr);
                }
            uint32_t Bf[NB][2];
            #pragma unroll
            for (int nb2 = 0; nb2 < NB2; nb2++) {
                uint32_t r0, r1, r2, r3;
                uint32_t addr = smem_u32 + 2u * (uint32_t)(
                    B_BASE + st * B_STAGE + (0 * BN + wn0 + nb2 * 16 + lrow) * KSTRIDE + s16 + lcol);
                LDSM_X4(r0, r1, r2, r3, addr);
                Bf[2 * nb2][0] = r0;     Bf[2 * nb2][1] = r2;
                Bf[2 * nb2 + 1][0] = r1; Bf[2 * nb2 + 1][1] = r3;
            }
            #pragma unroll
            for (int mb = 0; mb < MB; mb++)
                #pragma unroll
                for (int nb = 0; nb < NB; nb++) {
                    MMA_16816(acc[mb][nb], Af[0][mb], Bf[nb]);
                    MMA_16816(acc[mb][nb], Af[1][mb], Bf[nb]);
                }
            #pragma unroll
            for (int nb2 = 0; nb2 < NB2; nb2++) {
                uint32_t r0, r1, r2, r3;
                uint32_t addr = smem_u32 + 2u * (uint32_t)(
                    B_BASE + st * B_STAGE + (1 * BN + wn0 + nb2 * 16 + lrow) * KSTRIDE + s16 + lcol);
                LDSM_X4(r0, r1, r2, r3, addr);
                Bf[2 * nb2][0] = r0;     Bf[2 * nb2][1] = r2;
                Bf[2 * nb2 + 1][0] = r1; Bf[2 * nb2 + 1][1] = r3;
            }
            #pragma unroll
            for (int mb = 0; mb < MB; mb++)
                #pragma unroll
                for (int nb = 0; nb < NB; nb++)
                    MMA_16816(acc[mb][nb], Af[0][mb], Bf[nb]);
        }
    }

    // ---------------- epilogue ----------------
    const int lr = lane >> 2;
    const int lc = (lane & 3) * 2;
    #pragma unroll
    for (int mb = 0; mb < MB; mb++) {
        #pragma unroll
        for (int rr2 = 0; rr2 < 2; rr2++) {
            const int rg = row0 + wm0 + mb * 16 + lr + rr2 * 8;
            float ra = 0.f, tm[NC];
            if (MODE != 0) ra = __ldg(&rnA[rg]);
            if (MODE == 2) {
                #pragma unroll
                for (int cc = 0; cc < NC; cc++) tm[cc] = sTm[(rg - row0) * NC + cc];
            }
            #pragma unroll
            for (int nb = 0; nb < NB; nb++) {
                const int cg = col0 + wn0 + nb * 8 + lc;
                float v0 = acc[mb][nb][rr2 * 2];
                float v1 = acc[mb][nb][rr2 * 2 + 1];
                if (MODE != 0) {
                    float rb0 = __ldg(&rnB[cg]);
                    float rb1 = __ldg(&rnB[cg + 1]);
                    float d0 = sqrtf(fmaxf(ra + rb0 - 2.f * v0, 1e-12f));
                    float d1 = sqrtf(fmaxf(ra + rb1 - 2.f * v1, 1e-12f));
                    if (MODE == 2) {
                        float l0 = 0.f, l1 = 0.f;
                        #pragma unroll
                        for (int cc = 0; cc < NC; cc++) {
                            l0 = fmaf(tm[cc], sShl[(cg - col0) * NC + cc], l0);
                            l1 = fmaf(tm[cc], sShl[(cg + 1 - col0) * NC + cc], l1);
                        }
                        d0 += l0; d1 += l1;
                    }
                    v0 = -TEMP * d0; v1 = -TEMP * d1;
                }
                *reinterpret_cast<float2*>(&Cz[(size_t)rg * N + cg]) = make_float2(v0, v1);
            }
        }
    }
}

// ===================== fused row softmax + split2 (fp16 hi/lo weights) =====================
template<int NCOL, int THREADS>
__global__ void softmax_split_kernel(const float* __restrict__ X,
                                     __half* __restrict__ W0,
                                     __half* __restrict__ W1) {
    constexpr int PER = NCOL / THREADS;
    int row = blockIdx.x;
    const float* xr = X + (size_t)row * NCOL;
    int tid = threadIdx.x;
    float r[PER];
    float mx = -INFINITY;
    #pragma unroll
    for (int i = 0; i < PER; i++) {
        r[i] = xr[tid + i * THREADS];
        mx = fmaxf(mx, r[i]);
    }
    __shared__ float sred[THREADS / 32];
    #pragma unroll
    for (int o = 16; o > 0; o >>= 1) mx = fmaxf(mx, __shfl_xor_sync(0xffffffffu, mx, o));
    if ((tid & 31) == 0) sred[tid >> 5] = mx;
    __syncthreads();
    {
        float m = sred[0];
        #pragma unroll
        for (int i = 1; i < THREADS / 32; i++) m = fmaxf(m, sred[i]);
        mx = m;
    }
    __syncthreads();
    float s = 0.f;
    #pragma unroll
    for (int i = 0; i < PER; i++) {
        r[i] = expf(r[i] - mx);
        s += r[i];
    }
    #pragma unroll
    for (int o = 16; o > 0; o >>= 1) s += __shfl_xor_sync(0xffffffffu, s, o);
    if ((tid & 31) == 0) sred[tid >> 5] = s;
    __syncthreads();
    {
        float m = 0.f;
        #pragma unroll
        for (int i = 0; i < THREADS / 32; i++) m += sred[i];
        s = m;
    }
    float inv = 1.f / s;
    #pragma unroll
    for (int i = 0; i < PER; i++) {
        float wv = r[i] * inv;
        __half h, l;
        split2_one(wv, h, l);
        size_t o = (size_t)row * NCOL + tid + i * THREADS;
        W0[o] = h; W1[o] = l;
    }
}

// ===================== classifier head + split-K reduce + x_src split-2 =====================
__global__ void preds_kernel(const float* __restrict__ xsp, const float* __restrict__ W,
                             const float* __restrict__ b, const float* __restrict__ L,
                             float* __restrict__ t_out, float* __restrict__ xsn,
                             __half* __restrict__ XS0, __half* __restrict__ XS1)
{
    int row = blockIdx.x;
    int tid = threadIdx.x;
    float acc[NC];
    #pragma unroll
    for (int c = 0; c < NC; c++) acc[c] = 0.f;
    float nrm = 0.f;
    for (int k = tid; k < DIM; k += blockDim.x) {
        size_t o = (size_t)row * DIM + k;
        float xv = 0.f;
        #pragma unroll
        for (int z = 0; z < SPLITK; z++)
            xv += xsp[(size_t)z * BATCH * DIM + o];
        nrm = fmaf(xv, xv, nrm);
        __half h, l;
        split2_one(xv, h, l);
        XS0[o] = h; XS1[o] = l;
        #pragma unroll
        for (int c = 0; c < NC; c++) acc[c] = fmaf(xv, __ldg(&W[k * NC + c]), acc[c]);
    }
    __shared__ float red[NC + 1][128];
    #pragma unroll
    for (int c = 0; c < NC; c++) red[c][tid] = acc[c];
    red[NC][tid] = nrm;
    __syncthreads();
    for (int st = 64; st > 0; st >>= 1) {
        if (tid < st) {
            #pragma unroll
            for (int c = 0; c <= NC; c++) red[c][tid] += red[c][tid + st];
        }
        __syncthreads();
    }
    if (tid == 0) {
        float lg[NC], m = -INFINITY, s = 0.f;
        #pragma unroll
        for (int c = 0; c < NC; c++) { lg[c] = red[c][0] + b[c]; m = fmaxf(m, lg[c]); }
        #pragma unroll
        for (int c = 0; c < NC; c++) { lg[c] = expf(lg[c] - m); s += lg[c]; }
        float inv = 1.f / s;
        #pragma unroll
        for (int c = 0; c < NC; c++) {
            float tv = 0.f;
            #pragma unroll
            for (int cc = 0; cc < NC; cc++) tv = fmaf(lg[cc] * inv, L[cc * NC + c], tv);
            t_out[row * NC + c] = tv;
        }
        xsn[row] = red[NC][0];
    }
}

// ===================== fused softmax + (w @ atlT) =====================
__global__ void final_kernel(const float* __restrict__ logits, const float* __restrict__ atlT,
                             float* __restrict__ y)
{
    constexpr int THREADS = 512;
    constexpr int PER = NS / THREADS;   // 16
    int row = blockIdx.x;
    int tid = threadIdx.x;
    const float* xr = logits + (size_t)row * NS;
    float r[PER];
    float mx = -INFINITY;
    #pragma unroll
    for (int i = 0; i < PER; i++) {
        r[i] = xr[tid + i * THREADS];
        mx = fmaxf(mx, r[i]);
    }
    __shared__ float sred[THREADS / 32];
    #pragma unroll
    for (int o = 16; o > 0; o >>= 1) mx = fmaxf(mx, __shfl_xor_sync(0xffffffffu, mx, o));
    if ((tid & 31) == 0) sred[tid >> 5] = mx;
    __syncthreads();
    {
        float m = sred[0];
        #pragma unroll
        for (int i = 1; i < THREADS / 32; i++) m = fmaxf(m, sred[i]);
        mx = m;
    }
    __syncthreads();

    float s = 0.f;
    float e[PER];
    #pragma unroll
    for (int i = 0; i < PER; i++) {
        e[i] = expf(r[i] - mx);
        s += e[i];
    }
    float ya[NC];
    #pragma unroll
    for (int c = 0; c < NC; c++) {
        float a = 0.f;
        #pragma unroll
        for (int i = 0; i < PER; i++)
            a = fmaf(e[i], __ldg(&atlT[(size_t)c * NS + tid + i * THREADS]), a);
        ya[c] = a;
    }
    __shared__ float red[NC + 1][THREADS];
    #pragma unroll
    for (int c = 0; c < NC; c++) red[c][tid] = ya[c];
    red[NC][tid] = s;
    __syncthreads();
    for (int st = THREADS / 2; st > 0; st >>= 1) {
        if (tid < st) {
            #pragma unroll
            for (int c = 0; c <= NC; c++) red[c][tid] += red[c][tid + st];
        }
        __syncthreads();
    }
    if (tid < NC) {
        y[row * NC + tid] = red[tid][0] / red[NC][0];
    }
}

// ===================== launch =====================
extern "C" void kernel_launch(void* const* d_in, const int* in_sizes, int n_in,
                              void* d_out, int out_size)
{
    const float* x   = (const float*)d_in[0];
    const float* tf  = (const float*)d_in[1];
    const float* asf = (const float*)d_in[2];
    const float* sf  = (const float*)d_in[3];
    const float* shl = (const float*)d_in[4];
    const float* atl = (const float*)d_in[5];
    const float* sld = (const float*)d_in[6];
    const float* W   = (const float*)d_in[7];
    const float* b   = (const float*)d_in[8];
    float* y = (float*)d_out;

    float *logits, *xsp, *tn, *sn, *xn, *xsn, *tbuf, *atlT;
    __half *x2, *tf2, *sf2, *asfT2, *w2, *xs2;
    cudaGetSymbolAddress((void**)&logits, g_logits);
    cudaGetSymbolAddress((void**)&xsp,    g_xsp);
    cudaGetSymbolAddress((void**)&tn,     g_tn);
    cudaGetSymbolAddress((void**)&sn,     g_sn);
    cudaGetSymbolAddress((void**)&xn,     g_xn);
    cudaGetSymbolAddress((void**)&xsn,    g_xsn);
    cudaGetSymbolAddress((void**)&tbuf,   g_t);
    cudaGetSymbolAddress((void**)&atlT,   g_atlT);
    cudaGetSymbolAddress((void**)&x2,     g_x2);
    cudaGetSymbolAddress((void**)&tf2,    g_tf2);
    cudaGetSymbolAddress((void**)&sf2,    g_sf2);
    cudaGetSymbolAddress((void**)&asfT2,  g_asfT2);
    cudaGetSymbolAddress((void**)&w2,     g_w2);
    cudaGetSymbolAddress((void**)&xs2,    g_xs2);

    // smem: tiles = 2B * STAGES * 2*(BM+BN) * KSTRIDE; + label region for MODE2
    const int smem_gemm = 2 * 3 * 2 * (64 + 128) * KSTRIDE + (64 + 128) * NC * 4;  // 99840
    cudaFuncSetAttribute(mma_gemm_kernel<64, 128, 64, 32, 3, 1>,
                         cudaFuncAttributeMaxDynamicSharedMemorySize, smem_gemm);
    cudaFuncSetAttribute(mma_gemm_kernel<64, 128, 64, 32, 3, 2>,
                         cudaFuncAttributeMaxDynamicSharedMemorySize, smem_gemm);
    cudaFuncSetAttribute(mma_gemm_kernel<64, 128, 64, 32, 3, 0>,
                         cudaFuncAttributeMaxDynamicSharedMemorySize, smem_gemm);

    const size_t SZ_XD = (size_t)BATCH * DIM;
    const size_t SZ_TD = (size_t)NT * DIM;
    const size_t SZ_SD = (size_t)NS * DIM;
    const size_t SZ_DT = (size_t)DIM * NT;
    const size_t SZ_BN = (size_t)BATCH * NT;

    // 1) fused norm + split-2 (inputs needed by GEMM1 first; GEMM1 is launch #4
    //    so ncu's fixed capture slot profiles it next round)
    norm_split2_kernel<<<BATCH, 256>>>(x, x2, x2 + SZ_XD, xn);
    norm_split2_kernel<<<NT, 256>>>(tf, tf2, tf2 + SZ_TD, tn);
    norm_split2_kernel<<<NS, 256>>>(sf, sf2, sf2 + SZ_SD, sn);

    // 2) feature-transport logits: -T * cdist(xf, tf)   [1024 x 8192]
    //    64x128 tiles -> 1024 CTAs = 6.92 waves (98.8% wave eff)
    mma_gemm_kernel<64, 128, 64, 32, 3, 1>
        <<<dim3(NT / 128, BATCH / 64, 1), 128, smem_gemm>>>(
        x2, x2 + SZ_XD, tf2, tf2 + SZ_TD, logits, NT, DIM, 0,
        xn, tn, nullptr, nullptr);

    // 3) transposes (independent of GEMM1; needed later)
    split2T_kernel<<<dim3(DIM / 32, NT / 32), 256>>>(asf, asfT2, asfT2 + SZ_DT, NT, DIM);
    atlT_kernel<<<NS / 256, 256>>>(atl, atlT);

    // 4) softmax over Nt, emitting split-2 fp16 weights directly
    softmax_split_kernel<NT, 512><<<BATCH, 512>>>(logits, w2, w2 + SZ_BN);

    // 5) x_src partials = w_feat @ asf   [1024 x 1024], K = 8192, uneven split-K = 9
    //    grid 8*16*9 = 1152 CTAs = 7.78 waves (97.3% wave eff)
    mma_gemm_kernel<64, 128, 64, 32, 3, 0>
        <<<dim3(DIM / 128, BATCH / 64, SPLITK), 128, smem_gemm>>>(
        w2, w2 + SZ_BN, asfT2, asfT2 + SZ_DT, xsp, DIM, NT, SZ_XD,
        nullptr, nullptr, nullptr, nullptr);

    // 6) classifier head: reduce split-K partials -> preds@L, ||x_src||^2, x_src split-2
    preds_kernel<<<BATCH, 128>>>(xsp, W, b, sld, tbuf, xsn, xs2, xs2 + SZ_XD);

    // 7) label-transport logits  [1024 x 8192], 1024 CTAs
    mma_gemm_kernel<64, 128, 64, 32, 3, 2>
        <<<dim3(NS / 128, BATCH / 64, 1), 128, smem_gemm>>>(
        xs2, xs2 + SZ_XD, sf2, sf2 + SZ_SD, logits, NS, DIM, 0,
        xsn, sn, tbuf, shl);

    // 8) softmax over Ns fused with y = w_lab @ atlT
    final_kernel<<<BATCH, 512>>>(logits, atlT, y);
}

// round 14
// speedup vs baseline: 1.1993x; 1.1993x over previous
#include <cuda_runtime.h>
#include <cuda_fp16.h>
#include <math.h>
#include <stdint.h>

// ---------------- problem constants ----------------
#define BATCH 1024
#define NT    8192
#define NS    8192
#define DIM   1024
#define NC    10
#define TEMP  100.0f
#define SPLITK 9

// ---------------- scratch (device globals; no allocation) ----------------
__device__ float g_logits[(size_t)BATCH * NT];   // 32 MB
__device__ float g_xsp[(size_t)SPLITK * BATCH * DIM];  // split-K partials, 36 MB
__device__ float g_tn[NT];
__device__ float g_sn[NS];
__device__ float g_xn[BATCH];
__device__ float g_xsn[BATCH];
__device__ float g_t[BATCH * NC];
__device__ float g_atlT[NC * NS];                // atl transposed [NC, NS]
// fp16 split-2 operand buffers (hi at offset 0, lo at offset SZ)
__device__ __half g_x2  [(size_t)2 * BATCH * DIM];
__device__ __half g_tf2 [(size_t)2 * NT * DIM];
__device__ __half g_sf2 [(size_t)2 * NS * DIM];
__device__ __half g_asfT2[(size_t)2 * DIM * NT];   // asf transposed: [DIM, NT]
__device__ __half g_w2  [(size_t)2 * BATCH * NT];
__device__ __half g_xs2 [(size_t)2 * BATCH * DIM];

// ===================== asm helpers (sm_80-era PTX; compiles for compute_103) =====================
__device__ __forceinline__ uint32_t smem_to_u32(const void* smem_ptr) {
    uint32_t addr;
    asm("{ .reg .u64 tmp; cvta.to.shared.u64 tmp, %1; cvt.u32.u64 %0, tmp; }"
        : "=r"(addr) : "l"(smem_ptr));
    return addr;
}
#define CP_ASYNC_CG16(dst, src) \
    asm volatile("cp.async.cg.shared.global [%0], [%1], 16;" :: "r"(dst), "l"(src))
#define CP_COMMIT() asm volatile("cp.async.commit_group;" ::: "memory")
#define CP_WAIT(n)  asm volatile("cp.async.wait_group %0;" :: "n"(n) : "memory")
#define LDSM_X4(r0, r1, r2, r3, addr) \
    asm volatile("ldmatrix.sync.aligned.m8n8.x4.shared.b16 {%0,%1,%2,%3}, [%4];" \
        : "=r"(r0), "=r"(r1), "=r"(r2), "=r"(r3) : "r"(addr))
#define MMA_16816(d, a, b) \
    asm volatile("mma.sync.aligned.m16n8k16.row.col.f32.f16.f16.f32 " \
        "{%0,%1,%2,%3}, {%4,%5,%6,%7}, {%8,%9}, {%0,%1,%2,%3};" \
        : "+f"((d)[0]), "+f"((d)[1]), "+f"((d)[2]), "+f"((d)[3]) \
        : "r"((a)[0]), "r"((a)[1]), "r"((a)[2]), "r"((a)[3]), \
          "r"((b)[0]), "r"((b)[1]))

// ===================== fp16 split-2 =====================
__device__ __forceinline__ void split2_one(float x, __half& h0, __half& h1) {
    h0 = __float2half_rn(x);
    h1 = __float2half_rn(x - __half2float(h0));
}

// fused: row squared-norm + split-2 (one pass over X). X: [R, 1024]; 256 thr/row.
__global__ void norm_split2_kernel(const float* __restrict__ X,
                                   __half* __restrict__ O0,
                                   __half* __restrict__ O1,
                                   float* __restrict__ norms) {
    int row = blockIdx.x;
    int tid = threadIdx.x;
    const float* xr = X + (size_t)row * DIM;
    float4 v = *reinterpret_cast<const float4*>(xr + tid * 4);
    float s = v.x * v.x + v.y * v.y + v.z * v.z + v.w * v.w;
    __half a0, a1, b0, b1, c0, c1, d0, d1;
    split2_one(v.x, a0, a1);
    split2_one(v.y, b0, b1);
    split2_one(v.z, c0, c1);
    split2_one(v.w, d0, d1);
    size_t o = (size_t)row * DIM + tid * 4;
    *reinterpret_cast<__half2*>(O0 + o)     = __halves2half2(a0, b0);
    *reinterpret_cast<__half2*>(O0 + o + 2) = __halves2half2(c0, d0);
    *reinterpret_cast<__half2*>(O1 + o)     = __halves2half2(a1, b1);
    *reinterpret_cast<__half2*>(O1 + o + 2) = __halves2half2(c1, d1);
    #pragma unroll
    for (int off = 16; off > 0; off >>= 1) s += __shfl_xor_sync(0xffffffffu, s, off);
    __shared__ float ws[8];
    if ((tid & 31) == 0) ws[tid >> 5] = s;
    __syncthreads();
    if (tid == 0) {
        float t = 0.f;
        #pragma unroll
        for (int i = 0; i < 8; i++) t += ws[i];
        norms[row] = t;
    }
}

// transpose + split2: X [R, Cc] fp32 -> O* [Cc, R] fp16.  32x32 tiles, 256 threads.
__global__ void split2T_kernel(const float* __restrict__ X,
                               __half* __restrict__ O0,
                               __half* __restrict__ O1, int R, int Cc) {
    __shared__ float t[32][33];
    int tx = threadIdx.x & 31;
    int ty = threadIdx.x >> 5;
    int r0 = blockIdx.y * 32;
    int c0 = blockIdx.x * 32;
    #pragma unroll
    for (int yy = 0; yy < 4; yy++) {
        int r = ty * 4 + yy;
        t[r][tx] = X[(size_t)(r0 + r) * Cc + c0 + tx];
    }
    __syncthreads();
    int p = tx & 15;
    int half = tx >> 4;
    #pragma unroll
    for (int yy = 0; yy < 2; yy++) {
        int j = ty * 2 + half + yy * 16;
        float v0 = t[p * 2][j], v1 = t[p * 2 + 1][j];
        __half h0, l0, h1, l1;
        split2_one(v0, h0, l0);
        split2_one(v1, h1, l1);
        size_t o = (size_t)(c0 + j) * R + r0 + p * 2;
        *reinterpret_cast<__half2*>(O0 + o) = __halves2half2(h0, h1);
        *reinterpret_cast<__half2*>(O1 + o) = __halves2half2(l0, l1);
    }
}

// tiny: atl [NS, NC] -> atlT [NC, NS]
__global__ void atlT_kernel(const float* __restrict__ atl, float* __restrict__ atlT) {
    int j = blockIdx.x * blockDim.x + threadIdx.x;
    if (j >= NS) return;
    #pragma unroll
    for (int c = 0; c < NC; c++) atlT[(size_t)c * NS + j] = atl[(size_t)j * NC + c];
}

// ===================== mma.sync fp16 split-2 GEMM (uneven split-K capable) =====================
// acc = A0*B0 + A0*B1 + A1*B0   (A = A0 + A1, B = B0 + B1; drop A1*B1)
// MODE 0: C = acc;  MODE 1: C = -T*sqrt(...);  MODE 2: MODE1 + label cost
// Occupancy-first config: 8 warps/CTA, 2 stages, 69KB smem -> 3 CTAs/SM = 24 warps/SM.
#define KSTRIDE 40   // 32 used + 8 pad (fp16 elems) -> conflict-free ldmatrix

template<int BM, int BN, int THREADS, int STAGES>
__device__ __forceinline__ void load_stage_fn(
    const __half* __restrict__ A0g, const __half* __restrict__ A1g,
    const __half* __restrict__ B0g, const __half* __restrict__ B1g,
    uint32_t smem_u32, int st, int k0, int row0, int col0, int K, int tid)
{
    constexpr int A_STAGE = 2 * BM * KSTRIDE;
    constexpr int B_STAGE = 2 * BN * KSTRIDE;
    constexpr int B_BASE  = STAGES * A_STAGE;
    constexpr int TOT_A = BM * 8;
    constexpr int CPT = (BM + BN) * 8 / THREADS;
    #pragma unroll
    for (int t = 0; t < CPT; t++) {
        int i = tid + t * THREADS;
        if (i < TOT_A) {
            int sp = i / (BM * 4);
            int rr = (i >> 2) % BM;
            int kc = i & 3;
            const __half* g = sp ? A1g : A0g;
            const __half* src = g + (size_t)(row0 + rr) * K + k0 + kc * 8;
            uint32_t dst = smem_u32 + 2u * (uint32_t)(
                st * A_STAGE + (sp * BM + rr) * KSTRIDE + kc * 8);
            CP_ASYNC_CG16(dst, src);
        } else {
            int j = i - TOT_A;
            int sp = j / (BN * 4);
            int rr = (j >> 2) % BN;
            int kc = j & 3;
            const __half* g = sp ? B1g : B0g;
            const __half* src = g + (size_t)(col0 + rr) * K + k0 + kc * 8;
            uint32_t dst = smem_u32 + 2u * (uint32_t)(
                B_BASE + st * B_STAGE + (sp * BN + rr) * KSTRIDE + kc * 8);
            CP_ASYNC_CG16(dst, src);
        }
    }
}

template<int BM, int BN, int WM, int WN, int STAGES, int MODE>
__global__ void __launch_bounds__((BM / WM) * (BN / WN) * 32, 3)
mma_gemm_kernel(const __half* __restrict__ A0g, const __half* __restrict__ A1g,
                const __half* __restrict__ B0g, const __half* __restrict__ B1g,
                float* __restrict__ C, int N, int K, size_t czstride,
                const float* __restrict__ rnA, const float* __restrict__ rnB,
                const float* __restrict__ Tm, const float* __restrict__ SHL)
{
    constexpr int THREADS = (BM / WM) * (BN / WN) * 32;
    constexpr int MB = WM / 16;
    constexpr int NB = WN / 8;
    constexpr int NB2 = WN / 16;
    constexpr int A_STAGE = 2 * BM * KSTRIDE;
    constexpr int B_STAGE = 2 * BN * KSTRIDE;
    constexpr int B_BASE  = STAGES * A_STAGE;
    constexpr int TILE_ELEMS = STAGES * (A_STAGE + B_STAGE);

    extern __shared__ char smem[];
    const uint32_t smem_u32 = smem_to_u32(smem);
    const int tid = threadIdx.x;
    const int wid = tid >> 5;
    const int lane = tid & 31;
    const int warps_n = BN / WN;
    const int wm0 = (wid / warps_n) * WM;
    const int wn0 = (wid % warps_n) * WN;
    const int row0 = blockIdx.y * BM;
    const int col0 = blockIdx.x * BN;

    // uneven split-K: distribute (K/32) chunks over gridDim.z
    const int tc = K >> 5;
    const int zb = tc / gridDim.z;
    const int zr = tc % gridDim.z;
    const int z  = blockIdx.z;
    const int nch   = zb + (z < (int)zr ? 1 : 0);
    const int kbase = 32 * (z * zb + (z < (int)zr ? z : (int)zr));
    float* Cz = C + (size_t)z * czstride;

    float* sTm  = reinterpret_cast<float*>(smem + 2 * TILE_ELEMS);
    float* sShl = sTm + BM * NC;
    if (MODE == 2) {
        for (int i = tid; i < BM * NC; i += THREADS)
            sTm[i] = __ldg(&Tm[(size_t)(row0 + i / NC) * NC + (i % NC)]);
        for (int i = tid; i < BN * NC; i += THREADS)
            sShl[i] = __ldg(&SHL[(size_t)(col0 + i / NC) * NC + (i % NC)]);
    }

    float acc[MB][NB][4];
    #pragma unroll
    for (int i = 0; i < MB; i++)
        #pragma unroll
        for (int j = 0; j < NB; j++)
            #pragma unroll
            for (int q = 0; q < 4; q++) acc[i][j][q] = 0.f;

    #pragma unroll
    for (int s = 0; s < STAGES - 1; s++) {
        if (s < nch) {
            load_stage_fn<BM, BN, THREADS, STAGES>(A0g, A1g, B0g, B1g, smem_u32,
                                                   s, kbase + (s << 5), row0, col0, K, tid);
        }
        CP_COMMIT();
    }

    const int lrow = lane & 15;
    const int lcol = (lane >> 4) << 3;

    for (int c = 0; c < nch; c++) {
        CP_WAIT(STAGES - 2);
        __syncthreads();
        int pf = c + STAGES - 1;
        if (pf < nch)
            load_stage_fn<BM, BN, THREADS, STAGES>(A0g, A1g, B0g, B1g, smem_u32,
                                                   pf % STAGES, kbase + (pf << 5),
                                                   row0, col0, K, tid);
        CP_COMMIT();
        const int st = c % STAGES;

        #pragma unroll
        for (int s16 = 0; s16 < 32; s16 += 16) {
            uint32_t Af[2][MB][4];
            #pragma unroll
            for (int sp = 0; sp < 2; sp++)
                #pragma unroll
                for (int mb = 0; mb < MB; mb++) {
                    uint32_t addr = smem_u32 + 2u * (uint32_t)(
                        st * A_STAGE + (sp * BM + wm0 + mb * 16 + lrow) * KSTRIDE + s16 + lcol);
                    LDSM_X4(Af[sp][mb][0], Af[sp][mb][1], Af[sp][mb][2], Af[sp][mb][3], addr);
                }
            uint32_t Bf[NB][2];
            #pragma unroll
            for (int nb2 = 0; nb2 < NB2; nb2++) {
                uint32_t r0, r1, r2, r3;
                uint32_t addr = smem_u32 + 2u * (uint32_t)(
                    B_BASE + st * B_STAGE + (0 * BN + wn0 + nb2 * 16 + lrow) * KSTRIDE + s16 + lcol);
                LDSM_X4(r0, r1, r2, r3, addr);
                Bf[2 * nb2][0] = r0;     Bf[2 * nb2][1] = r2;
                Bf[2 * nb2 + 1][0] = r1; Bf[2 * nb2 + 1][1] = r3;
            }
            #pragma unroll
            for (int mb = 0; mb < MB; mb++)
                #pragma unroll
                for (int nb = 0; nb < NB; nb++) {
                    MMA_16816(acc[mb][nb], Af[0][mb], Bf[nb]);
                    MMA_16816(acc[mb][nb], Af[1][mb], Bf[nb]);
                }
            #pragma unroll
            for (int nb2 = 0; nb2 < NB2; nb2++) {
                uint32_t r0, r1, r2, r3;
                uint32_t addr = smem_u32 + 2u * (uint32_t)(
                    B_BASE + st * B_STAGE + (1 * BN + wn0 + nb2 * 16 + lrow) * KSTRIDE + s16 + lcol);
                LDSM_X4(r0, r1, r2, r3, addr);
                Bf[2 * nb2][0] = r0;     Bf[2 * nb2][1] = r2;
                Bf[2 * nb2 + 1][0] = r1; Bf[2 * nb2 + 1][1] = r3;
            }
            #pragma unroll
            for (int mb = 0; mb < MB; mb++)
                #pragma unroll
                for (int nb = 0; nb < NB; nb++)
                    MMA_16816(acc[mb][nb], Af[0][mb], Bf[nb]);
        }
    }

    // ---------------- epilogue ----------------
    const int lr = lane >> 2;
    const int lc = (lane & 3) * 2;
    #pragma unroll
    for (int mb = 0; mb < MB; mb++) {
        #pragma unroll
        for (int rr2 = 0; rr2 < 2; rr2++) {
            const int rg = row0 + wm0 + mb * 16 + lr + rr2 * 8;
            float ra = 0.f, tm[NC];
            if (MODE != 0) ra = __ldg(&rnA[rg]);
            if (MODE == 2) {
                #pragma unroll
                for (int cc = 0; cc < NC; cc++) tm[cc] = sTm[(rg - row0) * NC + cc];
            }
            #pragma unroll
            for (int nb = 0; nb < NB; nb++) {
                const int cg = col0 + wn0 + nb * 8 + lc;
                float v0 = acc[mb][nb][rr2 * 2];
                float v1 = acc[mb][nb][rr2 * 2 + 1];
                if (MODE != 0) {
                    float rb0 = __ldg(&rnB[cg]);
                    float rb1 = __ldg(&rnB[cg + 1]);
                    float d0 = sqrtf(fmaxf(ra + rb0 - 2.f * v0, 1e-12f));
                    float d1 = sqrtf(fmaxf(ra + rb1 - 2.f * v1, 1e-12f));
                    if (MODE == 2) {
                        float l0 = 0.f, l1 = 0.f;
                        #pragma unroll
                        for (int cc = 0; cc < NC; cc++) {
                            l0 = fmaf(tm[cc], sShl[(cg - col0) * NC + cc], l0);
                            l1 = fmaf(tm[cc], sShl[(cg + 1 - col0) * NC + cc], l1);
                        }
                        d0 += l0; d1 += l1;
                    }
                    v0 = -TEMP * d0; v1 = -TEMP * d1;
                }
                *reinterpret_cast<float2*>(&Cz[(size_t)rg * N + cg]) = make_float2(v0, v1);
            }
        }
    }
}

// ===================== fused row softmax + split2 (fp16 hi/lo weights) =====================
template<int NCOL, int THREADS>
__global__ void softmax_split_kernel(const float* __restrict__ X,
                                     __half* __restrict__ W0,
                                     __half* __restrict__ W1) {
    constexpr int PER = NCOL / THREADS;
    int row = blockIdx.x;
    const float* xr = X + (size_t)row * NCOL;
    int tid = threadIdx.x;
    float r[PER];
    float mx = -INFINITY;
    #pragma unroll
    for (int i = 0; i < PER; i++) {
        r[i] = xr[tid + i * THREADS];
        mx = fmaxf(mx, r[i]);
    }
    __shared__ float sred[THREADS / 32];
    #pragma unroll
    for (int o = 16; o > 0; o >>= 1) mx = fmaxf(mx, __shfl_xor_sync(0xffffffffu, mx, o));
    if ((tid & 31) == 0) sred[tid >> 5] = mx;
    __syncthreads();
    {
        float m = sred[0];
        #pragma unroll
        for (int i = 1; i < THREADS / 32; i++) m = fmaxf(m, sred[i]);
        mx = m;
    }
    __syncthreads();
    float s = 0.f;
    #pragma unroll
    for (int i = 0; i < PER; i++) {
        r[i] = expf(r[i] - mx);
        s += r[i];
    }
    #pragma unroll
    for (int o = 16; o > 0; o >>= 1) s += __shfl_xor_sync(0xffffffffu, s, o);
    if ((tid & 31) == 0) sred[tid >> 5] = s;
    __syncthreads();
    {
        float m = 0.f;
        #pragma unroll
        for (int i = 0; i < THREADS / 32; i++) m += sred[i];
        s = m;
    }
    float inv = 1.f / s;
    #pragma unroll
    for (int i = 0; i < PER; i++) {
        float wv = r[i] * inv;
        __half h, l;
        split2_one(wv, h, l);
        size_t o = (size_t)row * NCOL + tid + i * THREADS;
        W0[o] = h; W1[o] = l;
    }
}

// ===================== classifier head + split-K reduce + x_src split-2 =====================
__global__ void preds_kernel(const float* __restrict__ xsp, const float* __restrict__ W,
                             const float* __restrict__ b, const float* __restrict__ L,
                             float* __restrict__ t_out, float* __restrict__ xsn,
                             __half* __restrict__ XS0, __half* __restrict__ XS1)
{
    int row = blockIdx.x;
    int tid = threadIdx.x;
    float acc[NC];
    #pragma unroll
    for (int c = 0; c < NC; c++) acc[c] = 0.f;
    float nrm = 0.f;
    for (int k = tid; k < DIM; k += blockDim.x) {
        size_t o = (size_t)row * DIM + k;
        float xv = 0.f;
        #pragma unroll
        for (int z = 0; z < SPLITK; z++)
            xv += xsp[(size_t)z * BATCH * DIM + o];
        nrm = fmaf(xv, xv, nrm);
        __half h, l;
        split2_one(xv, h, l);
        XS0[o] = h; XS1[o] = l;
        #pragma unroll
        for (int c = 0; c < NC; c++) acc[c] = fmaf(xv, __ldg(&W[k * NC + c]), acc[c]);
    }
    __shared__ float red[NC + 1][128];
    #pragma unroll
    for (int c = 0; c < NC; c++) red[c][tid] = acc[c];
    red[NC][tid] = nrm;
    __syncthreads();
    for (int st = 64; st > 0; st >>= 1) {
        if (tid < st) {
            #pragma unroll
            for (int c = 0; c <= NC; c++) red[c][tid] += red[c][tid + st];
        }
        __syncthreads();
    }
    if (tid == 0) {
        float lg[NC], m = -INFINITY, s = 0.f;
        #pragma unroll
        for (int c = 0; c < NC; c++) { lg[c] = red[c][0] + b[c]; m = fmaxf(m, lg[c]); }
        #pragma unroll
        for (int c = 0; c < NC; c++) { lg[c] = expf(lg[c] - m); s += lg[c]; }
        float inv = 1.f / s;
        #pragma unroll
        for (int c = 0; c < NC; c++) {
            float tv = 0.f;
            #pragma unroll
            for (int cc = 0; cc < NC; cc++) tv = fmaf(lg[cc] * inv, L[cc * NC + c], tv);
            t_out[row * NC + c] = tv;
        }
        xsn[row] = red[NC][0];
    }
}

// ===================== fused softmax + (w @ atlT) =====================
__global__ void final_kernel(const float* __restrict__ logits, const float* __restrict__ atlT,
                             float* __restrict__ y)
{
    constexpr int THREADS = 512;
    constexpr int PER = NS / THREADS;   // 16
    int row = blockIdx.x;
    int tid = threadIdx.x;
    const float* xr = logits + (size_t)row * NS;
    float r[PER];
    float mx = -INFINITY;
    #pragma unroll
    for (int i = 0; i < PER; i++) {
        r[i] = xr[tid + i * THREADS];
        mx = fmaxf(mx, r[i]);
    }
    __shared__ float sred[THREADS / 32];
    #pragma unroll
    for (int o = 16; o > 0; o >>= 1) mx = fmaxf(mx, __shfl_xor_sync(0xffffffffu, mx, o));
    if ((tid & 31) == 0) sred[tid >> 5] = mx;
    __syncthreads();
    {
        float m = sred[0];
        #pragma unroll
        for (int i = 1; i < THREADS / 32; i++) m = fmaxf(m, sred[i]);
        mx = m;
    }
    __syncthreads();

    float s = 0.f;
    float e[PER];
    #pragma unroll
    for (int i = 0; i < PER; i++) {
        e[i] = expf(r[i] - mx);
        s += e[i];
    }
    float ya[NC];
    #pragma unroll
    for (int c = 0; c < NC; c++) {
        float a = 0.f;
        #pragma unroll
        for (int i = 0; i < PER; i++)
            a = fmaf(e[i], __ldg(&atlT[(size_t)c * NS + tid + i * THREADS]), a);
        ya[c] = a;
    }
    __shared__ float red[NC + 1][THREADS];
    #pragma unroll
    for (int c = 0; c < NC; c++) red[c][tid] = ya[c];
    red[NC][tid] = s;
    __syncthreads();
    for (int st = THREADS / 2; st > 0; st >>= 1) {
        if (tid < st) {
            #pragma unroll
            for (int c = 0; c <= NC; c++) red[c][tid] += red[c][tid + st];
        }
        __syncthreads();
    }
    if (tid < NC) {
        y[row * NC + tid] = red[tid][0] / red[NC][0];
    }
}

// ===================== launch =====================
extern "C" void kernel_launch(void* const* d_in, const int* in_sizes, int n_in,
                              void* d_out, int out_size)
{
    const float* x   = (const float*)d_in[0];
    const float* tf  = (const float*)d_in[1];
    const float* asf = (const float*)d_in[2];
    const float* sf  = (const float*)d_in[3];
    const float* shl = (const float*)d_in[4];
    const float* atl = (const float*)d_in[5];
    const float* sld = (const float*)d_in[6];
    const float* W   = (const float*)d_in[7];
    const float* b   = (const float*)d_in[8];
    float* y = (float*)d_out;

    float *logits, *xsp, *tn, *sn, *xn, *xsn, *tbuf, *atlT;
    __half *x2, *tf2, *sf2, *asfT2, *w2, *xs2;
    cudaGetSymbolAddress((void**)&logits, g_logits);
    cudaGetSymbolAddress((void**)&xsp,    g_xsp);
    cudaGetSymbolAddress((void**)&tn,     g_tn);
    cudaGetSymbolAddress((void**)&sn,     g_sn);
    cudaGetSymbolAddress((void**)&xn,     g_xn);
    cudaGetSymbolAddress((void**)&xsn,    g_xsn);
    cudaGetSymbolAddress((void**)&tbuf,   g_t);
    cudaGetSymbolAddress((void**)&atlT,   g_atlT);
    cudaGetSymbolAddress((void**)&x2,     g_x2);
    cudaGetSymbolAddress((void**)&tf2,    g_tf2);
    cudaGetSymbolAddress((void**)&sf2,    g_sf2);
    cudaGetSymbolAddress((void**)&asfT2,  g_asfT2);
    cudaGetSymbolAddress((void**)&w2,     g_w2);
    cudaGetSymbolAddress((void**)&xs2,    g_xs2);

    // smem: tiles = 2B * STAGES(2) * 2*(BM+BN) * KSTRIDE; + label region for MODE2
    // = 2*2*2*(64+128)*40 + (64+128)*NC*4 = 61440 + 7680 = 69120 -> 3 CTAs/SM
    const int smem_gemm = 2 * 2 * 2 * (64 + 128) * KSTRIDE + (64 + 128) * NC * 4;
    cudaFuncSetAttribute(mma_gemm_kernel<64, 128, 32, 32, 2, 1>,
                         cudaFuncAttributeMaxDynamicSharedMemorySize, smem_gemm);
    cudaFuncSetAttribute(mma_gemm_kernel<64, 128, 32, 32, 2, 2>,
                         cudaFuncAttributeMaxDynamicSharedMemorySize, smem_gemm);
    cudaFuncSetAttribute(mma_gemm_kernel<64, 128, 32, 32, 2, 0>,
                         cudaFuncAttributeMaxDynamicSharedMemorySize, smem_gemm);

    const size_t SZ_XD = (size_t)BATCH * DIM;
    const size_t SZ_TD = (size_t)NT * DIM;
    const size_t SZ_SD = (size_t)NS * DIM;
    const size_t SZ_DT = (size_t)DIM * NT;
    const size_t SZ_BN = (size_t)BATCH * NT;

    // 1) fused norm + split-2 (one pass per input)
    norm_split2_kernel<<<BATCH, 256>>>(x, x2, x2 + SZ_XD, xn);
    norm_split2_kernel<<<NT, 256>>>(tf, tf2, tf2 + SZ_TD, tn);
    norm_split2_kernel<<<NS, 256>>>(sf, sf2, sf2 + SZ_SD, sn);

    // 2) feature-transport logits: -T * cdist(xf, tf)   [1024 x 8192]
    //    8 warps/CTA, 3 CTAs/SM -> 24 warps/SM
    mma_gemm_kernel<64, 128, 32, 32, 2, 1>
        <<<dim3(NT / 128, BATCH / 64, 1), 256, smem_gemm>>>(
        x2, x2 + SZ_XD, tf2, tf2 + SZ_TD, logits, NT, DIM, 0,
        xn, tn, nullptr, nullptr);

    // 3) transposes (independent of GEMM1; needed later)
    split2T_kernel<<<dim3(DIM / 32, NT / 32), 256>>>(asf, asfT2, asfT2 + SZ_DT, NT, DIM);
    atlT_kernel<<<NS / 256, 256>>>(atl, atlT);

    // 4) softmax over Nt, emitting split-2 fp16 weights directly
    softmax_split_kernel<NT, 512><<<BATCH, 512>>>(logits, w2, w2 + SZ_BN);

    // 5) x_src partials = w_feat @ asf   [1024 x 1024], K = 8192, uneven split-K = 9
    mma_gemm_kernel<64, 128, 32, 32, 2, 0>
        <<<dim3(DIM / 128, BATCH / 64, SPLITK), 256, smem_gemm>>>(
        w2, w2 + SZ_BN, asfT2, asfT2 + SZ_DT, xsp, DIM, NT, SZ_XD,
        nullptr, nullptr, nullptr, nullptr);

    // 6) classifier head: reduce split-K partials -> preds@L, ||x_src||^2, x_src split-2
    preds_kernel<<<BATCH, 128>>>(xsp, W, b, sld, tbuf, xsn, xs2, xs2 + SZ_XD);

    // 7) label-transport logits  [1024 x 8192]
    mma_gemm_kernel<64, 128, 32, 32, 2, 2>
        <<<dim3(NS / 128, BATCH / 64, 1), 256, smem_gemm>>>(
        xs2, xs2 + SZ_XD, sf2, sf2 + SZ_SD, logits, NS, DIM, 0,
        xsn, sn, tbuf, shl);

    // 8) softmax over Ns fused with y = w_lab @ atlT
    final_kernel<<<BATCH, 512>>>(logits, atlT, y);
}

// round 15
// speedup vs baseline: 1.3963x; 1.1643x over previous
#include <cuda_runtime.h>
#include <cuda_fp16.h>
#include <math.h>
#include <stdint.h>

// ---------------- problem constants ----------------
#define BATCH 1024
#define NT    8192
#define NS    8192
#define DIM   1024
#define NC    10
#define TEMP  100.0f
#define SPLITK 9

// ---------------- scratch (device globals; no allocation) ----------------
__device__ float g_logits[(size_t)BATCH * NT];   // 32 MB
__device__ float g_xsp[(size_t)SPLITK * BATCH * DIM];  // split-K partials, 36 MB
__device__ float g_tn[NT];
__device__ float g_sn[NS];
__device__ float g_xn[BATCH];
__device__ float g_xsn[BATCH];
__device__ float g_t[BATCH * NC];
__device__ float g_atlT[NC * NS];                // atl transposed [NC, NS]
// fp16 split-2 operand buffers (hi at offset 0, lo at offset SZ)
__device__ __half g_x2  [(size_t)2 * BATCH * DIM];
__device__ __half g_tf2 [(size_t)2 * NT * DIM];
__device__ __half g_sf2 [(size_t)2 * NS * DIM];
__device__ __half g_asfT2[(size_t)2 * DIM * NT];   // asf transposed: [DIM, NT]
__device__ __half g_w2  [(size_t)2 * BATCH * NT];
__device__ __half g_xs2 [(size_t)2 * BATCH * DIM];

// ===================== asm helpers (sm_80-era PTX; compiles for compute_103) =====================
__device__ __forceinline__ uint32_t smem_to_u32(const void* smem_ptr) {
    uint32_t addr;
    asm("{ .reg .u64 tmp; cvta.to.shared.u64 tmp, %1; cvt.u32.u64 %0, tmp; }"
        : "=r"(addr) : "l"(smem_ptr));
    return addr;
}
#define CP_ASYNC_CG16(dst, src) \
    asm volatile("cp.async.cg.shared.global [%0], [%1], 16;" :: "r"(dst), "l"(src))
#define CP_COMMIT() asm volatile("cp.async.commit_group;" ::: "memory")
#define CP_WAIT(n)  asm volatile("cp.async.wait_group %0;" :: "n"(n) : "memory")
#define LDSM_X4(r0, r1, r2, r3, addr) \
    asm volatile("ldmatrix.sync.aligned.m8n8.x4.shared.b16 {%0,%1,%2,%3}, [%4];" \
        : "=r"(r0), "=r"(r1), "=r"(r2), "=r"(r3) : "r"(addr))
#define MMA_16816(d, a, b) \
    asm volatile("mma.sync.aligned.m16n8k16.row.col.f32.f16.f16.f32 " \
        "{%0,%1,%2,%3}, {%4,%5,%6,%7}, {%8,%9}, {%0,%1,%2,%3};" \
        : "+f"((d)[0]), "+f"((d)[1]), "+f"((d)[2]), "+f"((d)[3]) \
        : "r"((a)[0]), "r"((a)[1]), "r"((a)[2]), "r"((a)[3]), \
          "r"((b)[0]), "r"((b)[1]))

// XOR swizzle: rows are 32 fp16 = 64B = 4 chunks of 16B. chunk ^= (row>>1)&3.
// ldmatrix 8-row phase hits bank-slots (row&1)*4 + (c ^ ((row>>1)&3)) — all 8 distinct.
#define SWZ_CHUNK(row, c) ((c) ^ (((row) >> 1) & 3))

// ===================== fp16 split-2 =====================
__device__ __forceinline__ void split2_one(float x, __half& h0, __half& h1) {
    h0 = __float2half_rn(x);
    h1 = __float2half_rn(x - __half2float(h0));
}

// fused: row squared-norm + split-2 (one pass over X). X: [R, 1024]; 256 thr/row.
__global__ void norm_split2_kernel(const float* __restrict__ X,
                                   __half* __restrict__ O0,
                                   __half* __restrict__ O1,
                                   float* __restrict__ norms) {
    int row = blockIdx.x;
    int tid = threadIdx.x;
    const float* xr = X + (size_t)row * DIM;
    float4 v = *reinterpret_cast<const float4*>(xr + tid * 4);
    float s = v.x * v.x + v.y * v.y + v.z * v.z + v.w * v.w;
    __half a0, a1, b0, b1, c0, c1, d0, d1;
    split2_one(v.x, a0, a1);
    split2_one(v.y, b0, b1);
    split2_one(v.z, c0, c1);
    split2_one(v.w, d0, d1);
    size_t o = (size_t)row * DIM + tid * 4;
    *reinterpret_cast<__half2*>(O0 + o)     = __halves2half2(a0, b0);
    *reinterpret_cast<__half2*>(O0 + o + 2) = __halves2half2(c0, d0);
    *reinterpret_cast<__half2*>(O1 + o)     = __halves2half2(a1, b1);
    *reinterpret_cast<__half2*>(O1 + o + 2) = __halves2half2(c1, d1);
    #pragma unroll
    for (int off = 16; off > 0; off >>= 1) s += __shfl_xor_sync(0xffffffffu, s, off);
    __shared__ float ws[8];
    if ((tid & 31) == 0) ws[tid >> 5] = s;
    __syncthreads();
    if (tid == 0) {
        float t = 0.f;
        #pragma unroll
        for (int i = 0; i < 8; i++) t += ws[i];
        norms[row] = t;
    }
}

// transpose + split2: X [R, Cc] fp32 -> O* [Cc, R] fp16.  32x32 tiles, 256 threads.
__global__ void split2T_kernel(const float* __restrict__ X,
                               __half* __restrict__ O0,
                               __half* __restrict__ O1, int R, int Cc) {
    __shared__ float t[32][33];
    int tx = threadIdx.x & 31;
    int ty = threadIdx.x >> 5;
    int r0 = blockIdx.y * 32;
    int c0 = blockIdx.x * 32;
    #pragma unroll
    for (int yy = 0; yy < 4; yy++) {
        int r = ty * 4 + yy;
        t[r][tx] = X[(size_t)(r0 + r) * Cc + c0 + tx];
    }
    __syncthreads();
    int p = tx & 15;
    int half = tx >> 4;
    #pragma unroll
    for (int yy = 0; yy < 2; yy++) {
        int j = ty * 2 + half + yy * 16;
        float v0 = t[p * 2][j], v1 = t[p * 2 + 1][j];
        __half h0, l0, h1, l1;
        split2_one(v0, h0, l0);
        split2_one(v1, h1, l1);
        size_t o = (size_t)(c0 + j) * R + r0 + p * 2;
        *reinterpret_cast<__half2*>(O0 + o) = __halves2half2(h0, h1);
        *reinterpret_cast<__half2*>(O1 + o) = __halves2half2(l0, l1);
    }
}

// tiny: atl [NS, NC] -> atlT [NC, NS]
__global__ void atlT_kernel(const float* __restrict__ atl, float* __restrict__ atlT) {
    int j = blockIdx.x * blockDim.x + threadIdx.x;
    if (j >= NS) return;
    #pragma unroll
    for (int c = 0; c < NC; c++) atlT[(size_t)c * NS + j] = atl[(size_t)j * NC + c];
}

// ===================== mma.sync fp16 split-2 GEMM (uneven split-K capable) =====================
// acc = A0*B0 + A0*B1 + A1*B0   (A = A0 + A1, B = B0 + B1; drop A1*B1)
// MODE 0: C = acc;  MODE 1: C = -T*sqrt(...);  MODE 2: MODE1 + label cost
// Occupancy-max config: 4 warps/CTA, 2 stages, XOR-swizzled 32KB smem -> 7 CTAs/SM.

template<int BM, int BN, int THREADS, int STAGES>
__device__ __forceinline__ void load_stage_fn(
    const __half* __restrict__ A0g, const __half* __restrict__ A1g,
    const __half* __restrict__ B0g, const __half* __restrict__ B1g,
    uint32_t smem_u32, int st, int k0, int row0, int col0, int K, int tid)
{
    constexpr int A_STAGE = 2 * BM * 32;
    constexpr int B_STAGE = 2 * BN * 32;
    constexpr int B_BASE  = STAGES * A_STAGE;
    constexpr int TOT_A = BM * 8;
    constexpr int CPT = (BM + BN) * 8 / THREADS;
    #pragma unroll
    for (int t = 0; t < CPT; t++) {
        int i = tid + t * THREADS;
        if (i < TOT_A) {
            int sp = i / (BM * 4);
            int rr = (i >> 2) % BM;
            int kc = i & 3;
            const __half* g = sp ? A1g : A0g;
            const __half* src = g + (size_t)(row0 + rr) * K + k0 + kc * 8;
            int srow = sp * BM + rr;
            uint32_t dst = smem_u32 + 2u * (uint32_t)(
                st * A_STAGE + srow * 32 + SWZ_CHUNK(srow, kc) * 8);
            CP_ASYNC_CG16(dst, src);
        } else {
            int j = i - TOT_A;
            int sp = j / (BN * 4);
            int rr = (j >> 2) % BN;
            int kc = j & 3;
            const __half* g = sp ? B1g : B0g;
            const __half* src = g + (size_t)(col0 + rr) * K + k0 + kc * 8;
            int srow = sp * BN + rr;
            uint32_t dst = smem_u32 + 2u * (uint32_t)(
                B_BASE + st * B_STAGE + srow * 32 + SWZ_CHUNK(srow, kc) * 8);
            CP_ASYNC_CG16(dst, src);
        }
    }
}

template<int BM, int BN, int WM, int WN, int STAGES, int MODE>
__global__ void __launch_bounds__((BM / WM) * (BN / WN) * 32, 7)
mma_gemm_kernel(const __half* __restrict__ A0g, const __half* __restrict__ A1g,
                const __half* __restrict__ B0g, const __half* __restrict__ B1g,
                float* __restrict__ C, int N, int K, size_t czstride,
                const float* __restrict__ rnA, const float* __restrict__ rnB,
                const float* __restrict__ Tm, const float* __restrict__ SHL)
{
    constexpr int THREADS = (BM / WM) * (BN / WN) * 32;
    constexpr int MB = WM / 16;
    constexpr int NB = WN / 8;
    constexpr int NB2 = WN / 16;
    constexpr int A_STAGE = 2 * BM * 32;
    constexpr int B_STAGE = 2 * BN * 32;
    constexpr int B_BASE  = STAGES * A_STAGE;

    extern __shared__ char smem[];
    const uint32_t smem_u32 = smem_to_u32(smem);
    const int tid = threadIdx.x;
    const int wid = tid >> 5;
    const int lane = tid & 31;
    const int warps_n = BN / WN;
    const int wm0 = (wid / warps_n) * WM;
    const int wn0 = (wid % warps_n) * WN;
    const int row0 = blockIdx.y * BM;
    const int col0 = blockIdx.x * BN;

    // uneven split-K: distribute (K/32) chunks over gridDim.z
    const int tc = K >> 5;
    const int zb = tc / gridDim.z;
    const int zr = tc % gridDim.z;
    const int z  = blockIdx.z;
    const int nch   = zb + (z < (int)zr ? 1 : 0);
    const int kbase = 32 * (z * zb + (z < (int)zr ? z : (int)zr));
    float* Cz = C + (size_t)z * czstride;

    float acc[MB][NB][4];
    #pragma unroll
    for (int i = 0; i < MB; i++)
        #pragma unroll
        for (int j = 0; j < NB; j++)
            #pragma unroll
            for (int q = 0; q < 4; q++) acc[i][j][q] = 0.f;

    #pragma unroll
    for (int s = 0; s < STAGES - 1; s++) {
        if (s < nch) {
            load_stage_fn<BM, BN, THREADS, STAGES>(A0g, A1g, B0g, B1g, smem_u32,
                                                   s, kbase + (s << 5), row0, col0, K, tid);
        }
        CP_COMMIT();
    }

    const int lrow = lane & 15;
    const int lc8  = (lane >> 4);        // 0 or 1: chunk sub-index from lane

    for (int c = 0; c < nch; c++) {
        CP_WAIT(STAGES - 2);
        __syncthreads();
        int pf = c + STAGES - 1;
        if (pf < nch)
            load_stage_fn<BM, BN, THREADS, STAGES>(A0g, A1g, B0g, B1g, smem_u32,
                                                   pf % STAGES, kbase + (pf << 5),
                                                   row0, col0, K, tid);
        CP_COMMIT();
        const int st = c % STAGES;

        #pragma unroll
        for (int s16 = 0; s16 < 2; s16++) {   // two K=16 halves; chunk base = s16*2
            uint32_t Af[2][MB][4];
            #pragma unroll
            for (int sp = 0; sp < 2; sp++)
                #pragma unroll
                for (int mb = 0; mb < MB; mb++) {
                    int row = sp * BM + wm0 + mb * 16 + lrow;
                    int ch = SWZ_CHUNK(row, s16 * 2 + lc8);
                    uint32_t addr = smem_u32 + 2u * (uint32_t)(
                        st * A_STAGE + row * 32 + ch * 8);
                    LDSM_X4(Af[sp][mb][0], Af[sp][mb][1], Af[sp][mb][2], Af[sp][mb][3], addr);
                }
            uint32_t Bf[NB][2];
            #pragma unroll
            for (int nb2 = 0; nb2 < NB2; nb2++) {
                uint32_t r0, r1, r2, r3;
                int row = 0 * BN + wn0 + nb2 * 16 + lrow;
                int ch = SWZ_CHUNK(row, s16 * 2 + lc8);
                uint32_t addr = smem_u32 + 2u * (uint32_t)(
                    B_BASE + st * B_STAGE + row * 32 + ch * 8);
                LDSM_X4(r0, r1, r2, r3, addr);
                Bf[2 * nb2][0] = r0;     Bf[2 * nb2][1] = r2;
                Bf[2 * nb2 + 1][0] = r1; Bf[2 * nb2 + 1][1] = r3;
            }
            #pragma unroll
            for (int mb = 0; mb < MB; mb++)
                #pragma unroll
                for (int nb = 0; nb < NB; nb++) {
                    MMA_16816(acc[mb][nb], Af[0][mb], Bf[nb]);
                    MMA_16816(acc[mb][nb], Af[1][mb], Bf[nb]);
                }
            #pragma unroll
            for (int nb2 = 0; nb2 < NB2; nb2++) {
                uint32_t r0, r1, r2, r3;
                int row = 1 * BN + wn0 + nb2 * 16 + lrow;
                int ch = SWZ_CHUNK(row, s16 * 2 + lc8);
                uint32_t addr = smem_u32 + 2u * (uint32_t)(
                    B_BASE + st * B_STAGE + row * 32 + ch * 8);
                LDSM_X4(r0, r1, r2, r3, addr);
                Bf[2 * nb2][0] = r0;     Bf[2 * nb2][1] = r2;
                Bf[2 * nb2 + 1][0] = r1; Bf[2 * nb2 + 1][1] = r3;
            }
            #pragma unroll
            for (int mb = 0; mb < MB; mb++)
                #pragma unroll
                for (int nb = 0; nb < NB; nb++)
                    MMA_16816(acc[mb][nb], Af[0][mb], Bf[nb]);
        }
    }

    // ---------------- epilogue ----------------
    // MODE2: reuse tile smem (mainloop done) for label tables.
    float* sTm  = reinterpret_cast<float*>(smem);
    float* sShl = sTm + BM * NC;
    if (MODE == 2) {
        __syncthreads();   // all warps done reading tiles
        for (int i = tid; i < BM * NC; i += THREADS)
            sTm[i] = __ldg(&Tm[(size_t)(row0 + i / NC) * NC + (i % NC)]);
        for (int i = tid; i < BN * NC; i += THREADS)
            sShl[i] = __ldg(&SHL[(size_t)(col0 + i / NC) * NC + (i % NC)]);
        __syncthreads();
    }

    const int lr = lane >> 2;
    const int lc = (lane & 3) * 2;
    #pragma unroll
    for (int mb = 0; mb < MB; mb++) {
        #pragma unroll
        for (int rr2 = 0; rr2 < 2; rr2++) {
            const int rg = row0 + wm0 + mb * 16 + lr + rr2 * 8;
            float ra = 0.f, tm[NC];
            if (MODE != 0) ra = __ldg(&rnA[rg]);
            if (MODE == 2) {
                #pragma unroll
                for (int cc = 0; cc < NC; cc++) tm[cc] = sTm[(rg - row0) * NC + cc];
            }
            #pragma unroll
            for (int nb = 0; nb < NB; nb++) {
                const int cg = col0 + wn0 + nb * 8 + lc;
                float v0 = acc[mb][nb][rr2 * 2];
                float v1 = acc[mb][nb][rr2 * 2 + 1];
                if (MODE != 0) {
                    float rb0 = __ldg(&rnB[cg]);
                    float rb1 = __ldg(&rnB[cg + 1]);
                    float d0 = sqrtf(fmaxf(ra + rb0 - 2.f * v0, 1e-12f));
                    float d1 = sqrtf(fmaxf(ra + rb1 - 2.f * v1, 1e-12f));
                    if (MODE == 2) {
                        float l0 = 0.f, l1 = 0.f;
                        #pragma unroll
                        for (int cc = 0; cc < NC; cc++) {
                            l0 = fmaf(tm[cc], sShl[(cg - col0) * NC + cc], l0);
                            l1 = fmaf(tm[cc], sShl[(cg + 1 - col0) * NC + cc], l1);
                        }
                        d0 += l0; d1 += l1;
                    }
                    v0 = -TEMP * d0; v1 = -TEMP * d1;
                }
                *reinterpret_cast<float2*>(&Cz[(size_t)rg * N + cg]) = make_float2(v0, v1);
            }
        }
    }
}

// ===================== fused row softmax + split2 (fp16 hi/lo weights) =====================
template<int NCOL, int THREADS>
__global__ void softmax_split_kernel(const float* __restrict__ X,
                                     __half* __restrict__ W0,
                                     __half* __restrict__ W1) {
    constexpr int PER = NCOL / THREADS;
    int row = blockIdx.x;
    const float* xr = X + (size_t)row * NCOL;
    int tid = threadIdx.x;
    float r[PER];
    float mx = -INFINITY;
    #pragma unroll
    for (int i = 0; i < PER; i++) {
        r[i] = xr[tid + i * THREADS];
        mx = fmaxf(mx, r[i]);
    }
    __shared__ float sred[THREADS / 32];
    #pragma unroll
    for (int o = 16; o > 0; o >>= 1) mx = fmaxf(mx, __shfl_xor_sync(0xffffffffu, mx, o));
    if ((tid & 31) == 0) sred[tid >> 5] = mx;
    __syncthreads();
    {
        float m = sred[0];
        #pragma unroll
        for (int i = 1; i < THREADS / 32; i++) m = fmaxf(m, sred[i]);
        mx = m;
    }
    __syncthreads();
    float s = 0.f;
    #pragma unroll
    for (int i = 0; i < PER; i++) {
        r[i] = expf(r[i] - mx);
        s += r[i];
    }
    #pragma unroll
    for (int o = 16; o > 0; o >>= 1) s += __shfl_xor_sync(0xffffffffu, s, o);
    if ((tid & 31) == 0) sred[tid >> 5] = s;
    __syncthreads();
    {
        float m = 0.f;
        #pragma unroll
        for (int i = 0; i < THREADS / 32; i++) m += sred[i];
        s = m;
    }
    float inv = 1.f / s;
    #pragma unroll
    for (int i = 0; i < PER; i++) {
        float wv = r[i] * inv;
        __half h, l;
        split2_one(wv, h, l);
        size_t o = (size_t)row * NCOL + tid + i * THREADS;
        W0[o] = h; W1[o] = l;
    }
}

// ===================== classifier head + split-K reduce + x_src split-2 =====================
__global__ void preds_kernel(const float* __restrict__ xsp, const float* __restrict__ W,
                             const float* __restrict__ b, const float* __restrict__ L,
                             float* __restrict__ t_out, float* __restrict__ xsn,
                             __half* __restrict__ XS0, __half* __restrict__ XS1)
{
    int row = blockIdx.x;
    int tid = threadIdx.x;
    float acc[NC];
    #pragma unroll
    for (int c = 0; c < NC; c++) acc[c] = 0.f;
    float nrm = 0.f;
    for (int k = tid; k < DIM; k += blockDim.x) {
        size_t o = (size_t)row * DIM + k;
        float xv = 0.f;
        #pragma unroll
        for (int z = 0; z < SPLITK; z++)
            xv += xsp[(size_t)z * BATCH * DIM + o];
        nrm = fmaf(xv, xv, nrm);
        __half h, l;
        split2_one(xv, h, l);
        XS0[o] = h; XS1[o] = l;
        #pragma unroll
        for (int c = 0; c < NC; c++) acc[c] = fmaf(xv, __ldg(&W[k * NC + c]), acc[c]);
    }
    __shared__ float red[NC + 1][128];
    #pragma unroll
    for (int c = 0; c < NC; c++) red[c][tid] = acc[c];
    red[NC][tid] = nrm;
    __syncthreads();
    for (int st = 64; st > 0; st >>= 1) {
        if (tid < st) {
            #pragma unroll
            for (int c = 0; c <= NC; c++) red[c][tid] += red[c][tid + st];
        }
        __syncthreads();
    }
    if (tid == 0) {
        float lg[NC], m = -INFINITY, s = 0.f;
        #pragma unroll
        for (int c = 0; c < NC; c++) { lg[c] = red[c][0] + b[c]; m = fmaxf(m, lg[c]); }
        #pragma unroll
        for (int c = 0; c < NC; c++) { lg[c] = expf(lg[c] - m); s += lg[c]; }
        float inv = 1.f / s;
        #pragma unroll
        for (int c = 0; c < NC; c++) {
            float tv = 0.f;
            #pragma unroll
            for (int cc = 0; cc < NC; cc++) tv = fmaf(lg[cc] * inv, L[cc * NC + c], tv);
            t_out[row * NC + c] = tv;
        }
        xsn[row] = red[NC][0];
    }
}

// ===================== fused softmax + (w @ atlT) =====================
__global__ void final_kernel(const float* __restrict__ logits, const float* __restrict__ atlT,
                             float* __restrict__ y)
{
    constexpr int THREADS = 512;
    constexpr int PER = NS / THREADS;   // 16
    int row = blockIdx.x;
    int tid = threadIdx.x;
    const float* xr = logits + (size_t)row * NS;
    float r[PER];
    float mx = -INFINITY;
    #pragma unroll
    for (int i = 0; i < PER; i++) {
        r[i] = xr[tid + i * THREADS];
        mx = fmaxf(mx, r[i]);
    }
    __shared__ float sred[THREADS / 32];
    #pragma unroll
    for (int o = 16; o > 0; o >>= 1) mx = fmaxf(mx, __shfl_xor_sync(0xffffffffu, mx, o));
    if ((tid & 31) == 0) sred[tid >> 5] = mx;
    __syncthreads();
    {
        float m = sred[0];
        #pragma unroll
        for (int i = 1; i < THREADS / 32; i++) m = fmaxf(m, sred[i]);
        mx = m;
    }
    __syncthreads();

    float s = 0.f;
    float e[PER];
    #pragma unroll
    for (int i = 0; i < PER; i++) {
        e[i] = expf(r[i] - mx);
        s += e[i];
    }
    float ya[NC];
    #pragma unroll
    for (int c = 0; c < NC; c++) {
        float a = 0.f;
        #pragma unroll
        for (int i = 0; i < PER; i++)
            a = fmaf(e[i], __ldg(&atlT[(size_t)c * NS + tid + i * THREADS]), a);
        ya[c] = a;
    }
    __shared__ float red[NC + 1][THREADS];
    #pragma unroll
    for (int c = 0; c < NC; c++) red[c][tid] = ya[c];
    red[NC][tid] = s;
    __syncthreads();
    for (int st = THREADS / 2; st > 0; st >>= 1) {
        if (tid < st) {
            #pragma unroll
            for (int c = 0; c <= NC; c++) red[c][tid] += red[c][tid + st];
        }
        __syncthreads();
    }
    if (tid < NC) {
        y[row * NC + tid] = red[tid][0] / red[NC][0];
    }
}

// ===================== launch =====================
extern "C" void kernel_launch(void* const* d_in, const int* in_sizes, int n_in,
                              void* d_out, int out_size)
{
    const float* x   = (const float*)d_in[0];
    const float* tf  = (const float*)d_in[1];
    const float* asf = (const float*)d_in[2];
    const float* sf  = (const float*)d_in[3];
    const float* shl = (const float*)d_in[4];
    const float* atl = (const float*)d_in[5];
    const float* sld = (const float*)d_in[6];
    const float* W   = (const float*)d_in[7];
    const float* b   = (const float*)d_in[8];
    float* y = (float*)d_out;

    float *logits, *xsp, *tn, *sn, *xn, *xsn, *tbuf, *atlT;
    __half *x2, *tf2, *sf2, *asfT2, *w2, *xs2;
    cudaGetSymbolAddress((void**)&logits, g_logits);
    cudaGetSymbolAddress((void**)&xsp,    g_xsp);
    cudaGetSymbolAddress((void**)&tn,     g_tn);
    cudaGetSymbolAddress((void**)&sn,     g_sn);
    cudaGetSymbolAddress((void**)&xn,     g_xn);
    cudaGetSymbolAddress((void**)&xsn,    g_xsn);
    cudaGetSymbolAddress((void**)&tbuf,   g_t);
    cudaGetSymbolAddress((void**)&atlT,   g_atlT);
    cudaGetSymbolAddress((void**)&x2,     g_x2);
    cudaGetSymbolAddress((void**)&tf2,    g_tf2);
    cudaGetSymbolAddress((void**)&sf2,    g_sf2);
    cudaGetSymbolAddress((void**)&asfT2,  g_asfT2);
    cudaGetSymbolAddress((void**)&w2,     g_w2);
    cudaGetSymbolAddress((void**)&xs2,    g_xs2);

    // smem: tiles = 2B * STAGES(2) * 2*(BM+BN) * 32 (XOR swizzle, no padding)
    // = 2*2*2*(64+64)*32 = 32768 B -> 7 CTAs/SM. Label tables reuse tile smem.
    const int smem_gemm = 2 * 2 * 2 * (64 + 64) * 32;   // 32768
    cudaFuncSetAttribute(mma_gemm_kernel<64, 64, 32, 32, 2, 1>,
                         cudaFuncAttributeMaxDynamicSharedMemorySize, smem_gemm);
    cudaFuncSetAttribute(mma_gemm_kernel<64, 64, 32, 32, 2, 2>,
                         cudaFuncAttributeMaxDynamicSharedMemorySize, smem_gemm);
    cudaFuncSetAttribute(mma_gemm_kernel<64, 64, 32, 32, 2, 0>,
                         cudaFuncAttributeMaxDynamicSharedMemorySize, smem_gemm);

    const size_t SZ_XD = (size_t)BATCH * DIM;
    const size_t SZ_TD = (size_t)NT * DIM;
    const size_t SZ_SD = (size_t)NS * DIM;
    const size_t SZ_DT = (size_t)DIM * NT;
    const size_t SZ_BN = (size_t)BATCH * NT;

    // 1) fused norm + split-2 (one pass per input)
    norm_split2_kernel<<<BATCH, 256>>>(x, x2, x2 + SZ_XD, xn);
    norm_split2_kernel<<<NT, 256>>>(tf, tf2, tf2 + SZ_TD, tn);
    norm_split2_kernel<<<NS, 256>>>(sf, sf2, sf2 + SZ_SD, sn);

    // 2) feature-transport logits: -T * cdist(xf, tf)   [1024 x 8192]
    //    4 warps/CTA, 7 CTAs/SM -> 28 warps/SM; 2048 CTAs
    mma_gemm_kernel<64, 64, 32, 32, 2, 1>
        <<<dim3(NT / 64, BATCH / 64, 1), 128, smem_gemm>>>(
        x2, x2 + SZ_XD, tf2, tf2 + SZ_TD, logits, NT, DIM, 0,
        xn, tn, nullptr, nullptr);

    // 3) transposes (independent of GEMM1; needed later)
    split2T_kernel<<<dim3(DIM / 32, NT / 32), 256>>>(asf, asfT2, asfT2 + SZ_DT, NT, DIM);
    atlT_kernel<<<NS / 256, 256>>>(atl, atlT);

    // 4) softmax over Nt, emitting split-2 fp16 weights directly
    softmax_split_kernel<NT, 512><<<BATCH, 512>>>(logits, w2, w2 + SZ_BN);

    // 5) x_src partials = w_feat @ asf   [1024 x 1024], K = 8192, uneven split-K = 9
    mma_gemm_kernel<64, 64, 32, 32, 2, 0>
        <<<dim3(DIM / 64, BATCH / 64, SPLITK), 128, smem_gemm>>>(
        w2, w2 + SZ_BN, asfT2, asfT2 + SZ_DT, xsp, DIM, NT, SZ_XD,
        nullptr, nullptr, nullptr, nullptr);

    // 6) classifier head: reduce split-K partials -> preds@L, ||x_src||^2, x_src split-2
    preds_kernel<<<BATCH, 128>>>(xsp, W, b, sld, tbuf, xsn, xs2, xs2 + SZ_XD);

    // 7) label-transport logits  [1024 x 8192]
    mma_gemm_kernel<64, 64, 32, 32, 2, 2>
        <<<dim3(NS / 64, BATCH / 64, 1), 128, smem_gemm>>>(
        xs2, xs2 + SZ_XD, sf2, sf2 + SZ_SD, logits, NS, DIM, 0,
        xsn, sn, tbuf, shl);

    // 8) softmax over Ns fused with y = w_lab @ atlT
    final_kernel<<<BATCH, 512>>>(logits, atlT, y);
}

// round 16
// speedup vs baseline: 1.4342x; 1.0272x over previous
#include <cuda_runtime.h>
#include <cuda_fp16.h>
#include <math.h>
#include <stdint.h>

// ---------------- problem constants ----------------
#define BATCH 1024
#define NT    8192
#define NS    8192
#define DIM   1024
#define NC    10
#define TEMP  100.0f
#define SPLITK 9

// ---------------- scratch (device globals; no allocation) ----------------
__device__ float g_logits[(size_t)BATCH * NT];   // 32 MB
__device__ float g_xsp[(size_t)SPLITK * BATCH * DIM];  // split-K partials, 36 MB
__device__ float g_tn[NT];
__device__ float g_sn[NS];
__device__ float g_xn[BATCH];
__device__ float g_xsn[BATCH];
__device__ float g_t[BATCH * NC];
__device__ float g_atlT[NC * NS];                // atl transposed [NC, NS]
// fp16 split-2 operand buffers (hi at offset 0, lo at offset SZ)
__device__ __half g_x2  [(size_t)2 * BATCH * DIM];
__device__ __half g_tf2 [(size_t)2 * NT * DIM];
__device__ __half g_sf2 [(size_t)2 * NS * DIM];
__device__ __half g_asfT2[(size_t)2 * DIM * NT];   // asf transposed: [DIM, NT]
__device__ __half g_w2  [(size_t)2 * BATCH * NT];
__device__ __half g_xs2 [(size_t)2 * BATCH * DIM];

// ===================== asm helpers (sm_80-era PTX; compiles for compute_103) =====================
__device__ __forceinline__ uint32_t smem_to_u32(const void* smem_ptr) {
    uint32_t addr;
    asm("{ .reg .u64 tmp; cvta.to.shared.u64 tmp, %1; cvt.u32.u64 %0, tmp; }"
        : "=r"(addr) : "l"(smem_ptr));
    return addr;
}
#define CP_ASYNC_CG16(dst, src) \
    asm volatile("cp.async.cg.shared.global [%0], [%1], 16;" :: "r"(dst), "l"(src))
#define CP_COMMIT() asm volatile("cp.async.commit_group;" ::: "memory")
#define CP_WAIT(n)  asm volatile("cp.async.wait_group %0;" :: "n"(n) : "memory")
#define LDSM_X4(r0, r1, r2, r3, addr) \
    asm volatile("ldmatrix.sync.aligned.m8n8.x4.shared.b16 {%0,%1,%2,%3}, [%4];" \
        : "=r"(r0), "=r"(r1), "=r"(r2), "=r"(r3) : "r"(addr))
#define MMA_16816(d, a, b) \
    asm volatile("mma.sync.aligned.m16n8k16.row.col.f32.f16.f16.f32 " \
        "{%0,%1,%2,%3}, {%4,%5,%6,%7}, {%8,%9}, {%0,%1,%2,%3};" \
        : "+f"((d)[0]), "+f"((d)[1]), "+f"((d)[2]), "+f"((d)[3]) \
        : "r"((a)[0]), "r"((a)[1]), "r"((a)[2]), "r"((a)[3]), \
          "r"((b)[0]), "r"((b)[1]))

// XOR swizzle: rows are 32 fp16 = 64B = 4 chunks of 16B. chunk ^= (row>>1)&3.
#define SWZ_CHUNK(row, c) ((c) ^ (((row) >> 1) & 3))

// ===================== fp16 split-2 =====================
__device__ __forceinline__ void split2_one(float x, __half& h0, __half& h1) {
    h0 = __float2half_rn(x);
    h1 = __float2half_rn(x - __half2float(h0));
}

// fused: row squared-norm + split-2 (one pass over X). X: [R, 1024]; 256 thr/row.
__global__ void norm_split2_kernel(const float* __restrict__ X,
                                   __half* __restrict__ O0,
                                   __half* __restrict__ O1,
                                   float* __restrict__ norms) {
    int row = blockIdx.x;
    int tid = threadIdx.x;
    const float* xr = X + (size_t)row * DIM;
    float4 v = *reinterpret_cast<const float4*>(xr + tid * 4);
    float s = v.x * v.x + v.y * v.y + v.z * v.z + v.w * v.w;
    __half a0, a1, b0, b1, c0, c1, d0, d1;
    split2_one(v.x, a0, a1);
    split2_one(v.y, b0, b1);
    split2_one(v.z, c0, c1);
    split2_one(v.w, d0, d1);
    size_t o = (size_t)row * DIM + tid * 4;
    *reinterpret_cast<__half2*>(O0 + o)     = __halves2half2(a0, b0);
    *reinterpret_cast<__half2*>(O0 + o + 2) = __halves2half2(c0, d0);
    *reinterpret_cast<__half2*>(O1 + o)     = __halves2half2(a1, b1);
    *reinterpret_cast<__half2*>(O1 + o + 2) = __halves2half2(c1, d1);
    #pragma unroll
    for (int off = 16; off > 0; off >>= 1) s += __shfl_xor_sync(0xffffffffu, s, off);
    __shared__ float ws[8];
    if ((tid & 31) == 0) ws[tid >> 5] = s;
    __syncthreads();
    if (tid == 0) {
        float t = 0.f;
        #pragma unroll
        for (int i = 0; i < 8; i++) t += ws[i];
        norms[row] = t;
    }
}

// transpose + split2: X [R, Cc] fp32 -> O* [Cc, R] fp16.  32x32 tiles, 256 threads.
__global__ void split2T_kernel(const float* __restrict__ X,
                               __half* __restrict__ O0,
                               __half* __restrict__ O1, int R, int Cc) {
    __shared__ float t[32][33];
    int tx = threadIdx.x & 31;
    int ty = threadIdx.x >> 5;
    int r0 = blockIdx.y * 32;
    int c0 = blockIdx.x * 32;
    #pragma unroll
    for (int yy = 0; yy < 4; yy++) {
        int r = ty * 4 + yy;
        t[r][tx] = X[(size_t)(r0 + r) * Cc + c0 + tx];
    }
    __syncthreads();
    int p = tx & 15;
    int half = tx >> 4;
    #pragma unroll
    for (int yy = 0; yy < 2; yy++) {
        int j = ty * 2 + half + yy * 16;
        float v0 = t[p * 2][j], v1 = t[p * 2 + 1][j];
        __half h0, l0, h1, l1;
        split2_one(v0, h0, l0);
        split2_one(v1, h1, l1);
        size_t o = (size_t)(c0 + j) * R + r0 + p * 2;
        *reinterpret_cast<__half2*>(O0 + o) = __halves2half2(h0, h1);
        *reinterpret_cast<__half2*>(O1 + o) = __halves2half2(l0, l1);
    }
}

// tiny: atl [NS, NC] -> atlT [NC, NS]
__global__ void atlT_kernel(const float* __restrict__ atl, float* __restrict__ atlT) {
    int j = blockIdx.x * blockDim.x + threadIdx.x;
    if (j >= NS) return;
    #pragma unroll
    for (int c = 0; c < NC; c++) atlT[(size_t)c * NS + j] = atl[(size_t)j * NC + c];
}

// ===================== mma.sync fp16 split-2 GEMM (uneven split-K capable) =====================
// acc = A0*B0 + A0*B1 + A1*B0   (A = A0 + A1, B = B0 + B1; drop A1*B1)
// MODE 0: C = acc;  MODE 1: C = -T*sqrt(...);  MODE 2: MODE1 + label cost
// Hoisted-address mainloop: per-iteration cost = add (+ xor) per LDSM/load only.

template<int BM, int BN, int WM, int WN, int STAGES, int MODE>
__global__ void __launch_bounds__((BM / WM) * (BN / WN) * 32, 6)
mma_gemm_kernel(const __half* __restrict__ A0g, const __half* __restrict__ A1g,
                const __half* __restrict__ B0g, const __half* __restrict__ B1g,
                float* __restrict__ C, int N, int K, size_t czstride,
                const float* __restrict__ rnA, const float* __restrict__ rnB,
                const float* __restrict__ Tm, const float* __restrict__ SHL)
{
    constexpr int THREADS = (BM / WM) * (BN / WN) * 32;
    constexpr int MB = WM / 16;
    constexpr int NB = WN / 8;
    constexpr int NB2 = WN / 16;
    constexpr int A_STAGE = 2 * BM * 32;       // elements per A stage
    constexpr int B_STAGE = 2 * BN * 32;
    constexpr int B_BASE  = STAGES * A_STAGE;  // element offset of B region
    static_assert(A_STAGE == B_STAGE, "stage byte strides must match");
    constexpr uint32_t SBYTES = 2u * A_STAGE;  // per-stage byte stride (A and B)
    constexpr int TOT_A = BM * 8;
    constexpr int CPT = (BM + BN) * 8 / THREADS;
    // compile-time source-array thresholds (unrolled t)
    constexpr int T_A0 = (BM * 4 + THREADS - 1) / THREADS;       // t < T_A0 -> A0g
    constexpr int T_A1 = (BM * 8 + THREADS - 1) / THREADS;       // t < T_A1 -> A1g
    constexpr int T_B0 = T_A1 + (BN * 4 + THREADS - 1) / THREADS; // t < T_B0 -> B0g
    static_assert((BM * 4) % THREADS == 0 && (BN * 4) % THREADS == 0, "clean split");

    extern __shared__ char smem[];
    const uint32_t smem_u32 = smem_to_u32(smem);
    const int tid = threadIdx.x;
    const int wid = tid >> 5;
    const int lane = tid & 31;
    const int warps_n = BN / WN;
    const int wm0 = (wid / warps_n) * WM;
    const int wn0 = (wid % warps_n) * WN;
    const int row0 = blockIdx.y * BM;
    const int col0 = blockIdx.x * BN;

    // uneven split-K: distribute (K/32) chunks over gridDim.z
    const int tc = K >> 5;
    const int zb = tc / gridDim.z;
    const int zr = tc % gridDim.z;
    const int z  = blockIdx.z;
    const int nch   = zb + (z < (int)zr ? 1 : 0);
    const int kbase = 32 * (z * zb + (z < (int)zr ? z : (int)zr));
    float* Cz = C + (size_t)z * czstride;

    // ---- hoisted loader offsets (loop-invariant) ----
    uint32_t goff[CPT];   // element offset into source matrix (k=0)
    uint32_t ldst[CPT];   // stage-0 smem byte address
    #pragma unroll
    for (int t = 0; t < CPT; t++) {
        int i = tid + t * THREADS;
        if (t < T_A1) {   // A side
            int rr = (i >> 2) & (BM - 1);
            int kc = i & 3;
            int srow = (t < T_A0 ? 0 : BM) + rr;
            goff[t] = (uint32_t)((row0 + rr) * K + kc * 8);
            ldst[t] = smem_u32 + 2u * (uint32_t)(srow * 32 + SWZ_CHUNK(srow, kc) * 8);
        } else {          // B side
            int j = i - TOT_A;
            int rr = (j >> 2) & (BN - 1);
            int kc = j & 3;
            int srow = (t < T_B0 ? 0 : BN) + rr;
            goff[t] = (uint32_t)((col0 + rr) * K + kc * 8);
            ldst[t] = smem_u32 + 2u * (uint32_t)(B_BASE + srow * 32 + SWZ_CHUNK(srow, kc) * 8);
        }
    }

    // ---- hoisted LDSM base addresses (stage 0, s16 = 0) ----
    const int lrow = lane & 15;
    const int lc8  = (lane >> 4);
    uint32_t aB[2][MB];
    #pragma unroll
    for (int sp = 0; sp < 2; sp++)
        #pragma unroll
        for (int mb = 0; mb < MB; mb++) {
            int row = sp * BM + wm0 + mb * 16 + lrow;
            aB[sp][mb] = smem_u32 + 2u * (uint32_t)(row * 32 + SWZ_CHUNK(row, lc8) * 8);
        }
    uint32_t bB[2][NB2];
    #pragma unroll
    for (int sp = 0; sp < 2; sp++)
        #pragma unroll
        for (int nb2 = 0; nb2 < NB2; nb2++) {
            int row = sp * BN + wn0 + nb2 * 16 + lrow;
            bB[sp][nb2] = smem_u32 + 2u * (uint32_t)(B_BASE + row * 32 + SWZ_CHUNK(row, lc8) * 8);
        }

    float acc[MB][NB][4];
    #pragma unroll
    for (int i = 0; i < MB; i++)
        #pragma unroll
        for (int j = 0; j < NB; j++)
            #pragma unroll
            for (int q = 0; q < 4; q++) acc[i][j][q] = 0.f;

    // prologue loads
    #pragma unroll
    for (int s = 0; s < STAGES - 1; s++) {
        if (s < nch) {
            int k0 = kbase + (s << 5);
            uint32_t sadd = s * SBYTES;
            #pragma unroll
            for (int t = 0; t < CPT; t++) {
                const __half* g = (t < T_A0) ? A0g : (t < T_A1) ? A1g
                                 : (t < T_B0) ? B0g : B1g;
                CP_ASYNC_CG16(ldst[t] + sadd, g + goff[t] + k0);
            }
        }
        CP_COMMIT();
    }

    for (int c = 0; c < nch; c++) {
        CP_WAIT(STAGES - 2);
        __syncthreads();
        int pf = c + STAGES - 1;
        if (pf < nch) {
            int k0 = kbase + (pf << 5);
            uint32_t sadd = (pf % STAGES) * SBYTES;
            #pragma unroll
            for (int t = 0; t < CPT; t++) {
                const __half* g = (t < T_A0) ? A0g : (t < T_A1) ? A1g
                                 : (t < T_B0) ? B0g : B1g;
                CP_ASYNC_CG16(ldst[t] + sadd, g + goff[t] + k0);
            }
        }
        CP_COMMIT();
        const uint32_t sadd = (c % STAGES) * SBYTES;

        #pragma unroll
        for (int s16 = 0; s16 < 2; s16++) {
            const uint32_t sxor = (uint32_t)(s16 << 5);   // chunk^2 == addr^32
            uint32_t Af[2][MB][4];
            #pragma unroll
            for (int sp = 0; sp < 2; sp++)
                #pragma unroll
                for (int mb = 0; mb < MB; mb++) {
                    uint32_t addr = (aB[sp][mb] + sadd) ^ sxor;
                    LDSM_X4(Af[sp][mb][0], Af[sp][mb][1], Af[sp][mb][2], Af[sp][mb][3], addr);
                }
            uint32_t Bf[NB][2];
            #pragma unroll
            for (int nb2 = 0; nb2 < NB2; nb2++) {
                uint32_t r0, r1, r2, r3;
                uint32_t addr = (bB[0][nb2] + sadd) ^ sxor;
                LDSM_X4(r0, r1, r2, r3, addr);
                Bf[2 * nb2][0] = r0;     Bf[2 * nb2][1] = r2;
                Bf[2 * nb2 + 1][0] = r1; Bf[2 * nb2 + 1][1] = r3;
            }
            #pragma unroll
            for (int mb = 0; mb < MB; mb++)
                #pragma unroll
                for (int nb = 0; nb < NB; nb++) {
                    MMA_16816(acc[mb][nb], Af[0][mb], Bf[nb]);
                    MMA_16816(acc[mb][nb], Af[1][mb], Bf[nb]);
                }
            #pragma unroll
            for (int nb2 = 0; nb2 < NB2; nb2++) {
                uint32_t r0, r1, r2, r3;
                uint32_t addr = (bB[1][nb2] + sadd) ^ sxor;
                LDSM_X4(r0, r1, r2, r3, addr);
                Bf[2 * nb2][0] = r0;     Bf[2 * nb2][1] = r2;
                Bf[2 * nb2 + 1][0] = r1; Bf[2 * nb2 + 1][1] = r3;
            }
            #pragma unroll
            for (int mb = 0; mb < MB; mb++)
                #pragma unroll
                for (int nb = 0; nb < NB; nb++)
                    MMA_16816(acc[mb][nb], Af[0][mb], Bf[nb]);
        }
    }

    // ---------------- epilogue ----------------
    // MODE2: reuse tile smem (mainloop done) for label tables.
    float* sTm  = reinterpret_cast<float*>(smem);
    float* sShl = sTm + BM * NC;
    if (MODE == 2) {
        __syncthreads();
        for (int i = tid; i < BM * NC; i += THREADS)
            sTm[i] = __ldg(&Tm[(size_t)(row0 + i / NC) * NC + (i % NC)]);
        for (int i = tid; i < BN * NC; i += THREADS)
            sShl[i] = __ldg(&SHL[(size_t)(col0 + i / NC) * NC + (i % NC)]);
        __syncthreads();
    }

    const int lr = lane >> 2;
    const int lc = (lane & 3) * 2;
    #pragma unroll
    for (int mb = 0; mb < MB; mb++) {
        #pragma unroll
        for (int rr2 = 0; rr2 < 2; rr2++) {
            const int rg = row0 + wm0 + mb * 16 + lr + rr2 * 8;
            float ra = 0.f, tm[NC];
            if (MODE != 0) ra = __ldg(&rnA[rg]);
            if (MODE == 2) {
                #pragma unroll
                for (int cc = 0; cc < NC; cc++) tm[cc] = sTm[(rg - row0) * NC + cc];
            }
            #pragma unroll
            for (int nb = 0; nb < NB; nb++) {
                const int cg = col0 + wn0 + nb * 8 + lc;
                float v0 = acc[mb][nb][rr2 * 2];
                float v1 = acc[mb][nb][rr2 * 2 + 1];
                if (MODE != 0) {
                    float rb0 = __ldg(&rnB[cg]);
                    float rb1 = __ldg(&rnB[cg + 1]);
                    float d0 = sqrtf(fmaxf(ra + rb0 - 2.f * v0, 1e-12f));
                    float d1 = sqrtf(fmaxf(ra + rb1 - 2.f * v1, 1e-12f));
                    if (MODE == 2) {
                        float l0 = 0.f, l1 = 0.f;
                        #pragma unroll
                        for (int cc = 0; cc < NC; cc++) {
                            l0 = fmaf(tm[cc], sShl[(cg - col0) * NC + cc], l0);
                            l1 = fmaf(tm[cc], sShl[(cg + 1 - col0) * NC + cc], l1);
                        }
                        d0 += l0; d1 += l1;
                    }
                    v0 = -TEMP * d0; v1 = -TEMP * d1;
                }
                *reinterpret_cast<float2*>(&Cz[(size_t)rg * N + cg]) = make_float2(v0, v1);
            }
        }
    }
}

// ===================== fused row softmax + split2 (fp16 hi/lo weights) =====================
template<int NCOL, int THREADS>
__global__ void softmax_split_kernel(const float* __restrict__ X,
                                     __half* __restrict__ W0,
                                     __half* __restrict__ W1) {
    constexpr int PER = NCOL / THREADS;
    int row = blockIdx.x;
    const float* xr = X + (size_t)row * NCOL;
    int tid = threadIdx.x;
    float r[PER];
    float mx = -INFINITY;
    #pragma unroll
    for (int i = 0; i < PER; i++) {
        r[i] = xr[tid + i * THREADS];
        mx = fmaxf(mx, r[i]);
    }
    __shared__ float sred[THREADS / 32];
    #pragma unroll
    for (int o = 16; o > 0; o >>= 1) mx = fmaxf(mx, __shfl_xor_sync(0xffffffffu, mx, o));
    if ((tid & 31) == 0) sred[tid >> 5] = mx;
    __syncthreads();
    {
        float m = sred[0];
        #pragma unroll
        for (int i = 1; i < THREADS / 32; i++) m = fmaxf(m, sred[i]);
        mx = m;
    }
    __syncthreads();
    float s = 0.f;
    #pragma unroll
    for (int i = 0; i < PER; i++) {
        r[i] = expf(r[i] - mx);
        s += r[i];
    }
    #pragma unroll
    for (int o = 16; o > 0; o >>= 1) s += __shfl_xor_sync(0xffffffffu, s, o);
    if ((tid & 31) == 0) sred[tid >> 5] = s;
    __syncthreads();
    {
        float m = 0.f;
        #pragma unroll
        for (int i = 0; i < THREADS / 32; i++) m += sred[i];
        s = m;
    }
    float inv = 1.f / s;
    #pragma unroll
    for (int i = 0; i < PER; i++) {
        float wv = r[i] * inv;
        __half h, l;
        split2_one(wv, h, l);
        size_t o = (size_t)row * NCOL + tid + i * THREADS;
        W0[o] = h; W1[o] = l;
    }
}

// ===================== classifier head + split-K reduce + x_src split-2 =====================
__global__ void preds_kernel(const float* __restrict__ xsp, const float* __restrict__ W,
                             const float* __restrict__ b, const float* __restrict__ L,
                             float* __restrict__ t_out, float* __restrict__ xsn,
                             __half* __restrict__ XS0, __half* __restrict__ XS1)
{
    int row = blockIdx.x;
    int tid = threadIdx.x;
    float acc[NC];
    #pragma unroll
    for (int c = 0; c < NC; c++) acc[c] = 0.f;
    float nrm = 0.f;
    for (int k = tid; k < DIM; k += blockDim.x) {
        size_t o = (size_t)row * DIM + k;
        float xv = 0.f;
        #pragma unroll
        for (int z = 0; z < SPLITK; z++)
            xv += xsp[(size_t)z * BATCH * DIM + o];
        nrm = fmaf(xv, xv, nrm);
        __half h, l;
        split2_one(xv, h, l);
        XS0[o] = h; XS1[o] = l;
        #pragma unroll
        for (int c = 0; c < NC; c++) acc[c] = fmaf(xv, __ldg(&W[k * NC + c]), acc[c]);
    }
    __shared__ float red[NC + 1][128];
    #pragma unroll
    for (int c = 0; c < NC; c++) red[c][tid] = acc[c];
    red[NC][tid] = nrm;
    __syncthreads();
    for (int st = 64; st > 0; st >>= 1) {
        if (tid < st) {
            #pragma unroll
            for (int c = 0; c <= NC; c++) red[c][tid] += red[c][tid + st];
        }
        __syncthreads();
    }
    if (tid == 0) {
        float lg[NC], m = -INFINITY, s = 0.f;
        #pragma unroll
        for (int c = 0; c < NC; c++) { lg[c] = red[c][0] + b[c]; m = fmaxf(m, lg[c]); }
        #pragma unroll
        for (int c = 0; c < NC; c++) { lg[c] = expf(lg[c] - m); s += lg[c]; }
        float inv = 1.f / s;
        #pragma unroll
        for (int c = 0; c < NC; c++) {
            float tv = 0.f;
            #pragma unroll
            for (int cc = 0; cc < NC; cc++) tv = fmaf(lg[cc] * inv, L[cc * NC + c], tv);
            t_out[row * NC + c] = tv;
        }
        xsn[row] = red[NC][0];
    }
}

// ===================== fused softmax + (w @ atlT) =====================
__global__ void final_kernel(const float* __restrict__ logits, const float* __restrict__ atlT,
                             float* __restrict__ y)
{
    constexpr int THREADS = 512;
    constexpr int PER = NS / THREADS;   // 16
    int row = blockIdx.x;
    int tid = threadIdx.x;
    const float* xr = logits + (size_t)row * NS;
    float r[PER];
    float mx = -INFINITY;
    #pragma unroll
    for (int i = 0; i < PER; i++) {
        r[i] = xr[tid + i * THREADS];
        mx = fmaxf(mx, r[i]);
    }
    __shared__ float sred[THREADS / 32];
    #pragma unroll
    for (int o = 16; o > 0; o >>= 1) mx = fmaxf(mx, __shfl_xor_sync(0xffffffffu, mx, o));
    if ((tid & 31) == 0) sred[tid >> 5] = mx;
    __syncthreads();
    {
        float m = sred[0];
        #pragma unroll
        for (int i = 1; i < THREADS / 32; i++) m = fmaxf(m, sred[i]);
        mx = m;
    }
    __syncthreads();

    float s = 0.f;
    float e[PER];
    #pragma unroll
    for (int i = 0; i < PER; i++) {
        e[i] = expf(r[i] - mx);
        s += e[i];
    }
    float ya[NC];
    #pragma unroll
    for (int c = 0; c < NC; c++) {
        float a = 0.f;
        #pragma unroll
        for (int i = 0; i < PER; i++)
            a = fmaf(e[i], __ldg(&atlT[(size_t)c * NS + tid + i * THREADS]), a);
        ya[c] = a;
    }
    __shared__ float red[NC + 1][THREADS];
    #pragma unroll
    for (int c = 0; c < NC; c++) red[c][tid] = ya[c];
    red[NC][tid] = s;
    __syncthreads();
    for (int st = THREADS / 2; st > 0; st >>= 1) {
        if (tid < st) {
            #pragma unroll
            for (int c = 0; c <= NC; c++) red[c][tid] += red[c][tid + st];
        }
        __syncthreads();
    }
    if (tid < NC) {
        y[row * NC + tid] = red[tid][0] / red[NC][0];
    }
}

// ===================== launch =====================
extern "C" void kernel_launch(void* const* d_in, const int* in_sizes, int n_in,
                              void* d_out, int out_size)
{
    const float* x   = (const float*)d_in[0];
    const float* tf  = (const float*)d_in[1];
    const float* asf = (const float*)d_in[2];
    const float* sf  = (const float*)d_in[3];
    const float* shl = (const float*)d_in[4];
    const float* atl = (const float*)d_in[5];
    const float* sld = (const float*)d_in[6];
    const float* W   = (const float*)d_in[7];
    const float* b   = (const float*)d_in[8];
    float* y = (float*)d_out;

    float *logits, *xsp, *tn, *sn, *xn, *xsn, *tbuf, *atlT;
    __half *x2, *tf2, *sf2, *asfT2, *w2, *xs2;
    cudaGetSymbolAddress((void**)&logits, g_logits);
    cudaGetSymbolAddress((void**)&xsp,    g_xsp);
    cudaGetSymbolAddress((void**)&tn,     g_tn);
    cudaGetSymbolAddress((void**)&sn,     g_sn);
    cudaGetSymbolAddress((void**)&xn,     g_xn);
    cudaGetSymbolAddress((void**)&xsn,    g_xsn);
    cudaGetSymbolAddress((void**)&tbuf,   g_t);
    cudaGetSymbolAddress((void**)&atlT,   g_atlT);
    cudaGetSymbolAddress((void**)&x2,     g_x2);
    cudaGetSymbolAddress((void**)&tf2,    g_tf2);
    cudaGetSymbolAddress((void**)&sf2,    g_sf2);
    cudaGetSymbolAddress((void**)&asfT2,  g_asfT2);
    cudaGetSymbolAddress((void**)&w2,     g_w2);
    cudaGetSymbolAddress((void**)&xs2,    g_xs2);

    // smem: tiles = 2B * STAGES(2) * 2*(BM+BN) * 32 (XOR swizzle) = 32768 B
    const int smem_gemm = 2 * 2 * 2 * (64 + 64) * 32;   // 32768
    cudaFuncSetAttribute(mma_gemm_kernel<64, 64, 32, 32, 2, 1>,
                         cudaFuncAttributeMaxDynamicSharedMemorySize, smem_gemm);
    cudaFuncSetAttribute(mma_gemm_kernel<64, 64, 32, 32, 2, 2>,
                         cudaFuncAttributeMaxDynamicSharedMemorySize, smem_gemm);
    cudaFuncSetAttribute(mma_gemm_kernel<64, 64, 32, 32, 2, 0>,
                         cudaFuncAttributeMaxDynamicSharedMemorySize, smem_gemm);

    const size_t SZ_XD = (size_t)BATCH * DIM;
    const size_t SZ_TD = (size_t)NT * DIM;
    const size_t SZ_SD = (size_t)NS * DIM;
    const size_t SZ_DT = (size_t)DIM * NT;
    const size_t SZ_BN = (size_t)BATCH * NT;

    // 1) fused norm + split-2 (one pass per input)
    norm_split2_kernel<<<BATCH, 256>>>(x, x2, x2 + SZ_XD, xn);
    norm_split2_kernel<<<NT, 256>>>(tf, tf2, tf2 + SZ_TD, tn);
    norm_split2_kernel<<<NS, 256>>>(sf, sf2, sf2 + SZ_SD, sn);

    // 2) feature-transport logits: -T * cdist(xf, tf)   [1024 x 8192]
    mma_gemm_kernel<64, 64, 32, 32, 2, 1>
        <<<dim3(NT / 64, BATCH / 64, 1), 128, smem_gemm>>>(
        x2, x2 + SZ_XD, tf2, tf2 + SZ_TD, logits, NT, DIM, 0,
        xn, tn, nullptr, nullptr);

    // 3) transposes (independent of GEMM1; needed later)
    split2T_kernel<<<dim3(DIM / 32, NT / 32), 256>>>(asf, asfT2, asfT2 + SZ_DT, NT, DIM);
    atlT_kernel<<<NS / 256, 256>>>(atl, atlT);

    // 4) softmax over Nt, emitting split-2 fp16 weights directly
    softmax_split_kernel<NT, 512><<<BATCH, 512>>>(logits, w2, w2 + SZ_BN);

    // 5) x_src partials = w_feat @ asf   [1024 x 1024], K = 8192, uneven split-K = 9
    mma_gemm_kernel<64, 64, 32, 32, 2, 0>
        <<<dim3(DIM / 64, BATCH / 64, SPLITK), 128, smem_gemm>>>(
        w2, w2 + SZ_BN, asfT2, asfT2 + SZ_DT, xsp, DIM, NT, SZ_XD,
        nullptr, nullptr, nullptr, nullptr);

    // 6) classifier head: reduce split-K partials -> preds@L, ||x_src||^2, x_src split-2
    preds_kernel<<<BATCH, 128>>>(xsp, W, b, sld, tbuf, xsn, xs2, xs2 + SZ_XD);

    // 7) label-transport logits  [1024 x 8192]
    mma_gemm_kernel<64, 64, 32, 32, 2, 2>
        <<<dim3(NS / 64, BATCH / 64, 1), 128, smem_gemm>>>(
        xs2, xs2 + SZ_XD, sf2, sf2 + SZ_SD, logits, NS, DIM, 0,
        xsn, sn, tbuf, shl);

    // 8) softmax over Ns fused with y = w_lab @ atlT
    final_kernel<<<BATCH, 512>>>(logits, atlT, y);
}